// round 11
// baseline (speedup 1.0000x reference)
#include <cuda_runtime.h>
#include <cuda_bf16.h>
#include <cstdint>

#define N_USER 100000
#define N_SPOT 100000
#define F_IN   64
#define HID    128
#define OUTC   64
#define EDG    500000
#define LEAK   0.2f
#define EPSF   1e-6f

// ---------------------------------------------------------------------------
// Scratch (device globals; no allocation allowed)
// ---------------------------------------------------------------------------
__device__ float g_srcA[(size_t)N_USER * HID];
__device__ float g_tgtA[(size_t)N_SPOT * HID];
__device__ float g_srcB[(size_t)N_SPOT * HID];
__device__ float g_tgtB[(size_t)N_USER * HID];
__device__ float g_hu[(size_t)N_USER * HID];
__device__ float g_hs[(size_t)N_SPOT * HID];

__device__ float g_alsA[N_USER];
__device__ float g_altA[N_SPOT];
__device__ float g_alsB[N_SPOT];
__device__ float g_altB[N_USER];

__device__ int g_si2_us[EDG];
__device__ int g_si2_su[EDG];
__device__ int g_cnt_us[N_SPOT + 1];
__device__ int g_off_us[N_SPOT + 1];
__device__ int g_cur_us[N_SPOT + 1];
__device__ int g_cnt_su[N_USER + 1];
__device__ int g_off_su[N_USER + 1];
__device__ int g_cur_su[N_USER + 1];
__device__ int g_csr_us[EDG];
__device__ int g_csr_su[EDG];
__device__ int g_row_us[EDG];
__device__ int g_row_su[EDG];
__device__ float g_att[EDG];

__device__ __forceinline__ float f2tf32(float x) {
    float y;
    asm("cvt.rna.tf32.f32 %0, %1;" : "=f"(y) : "f"(x));
    return y;
}
__device__ __forceinline__ uint32_t smem_u32(const void* p) {
    uint32_t a;
    asm("{ .reg .u64 t; cvta.to.shared.u64 t, %1; cvt.u32.u64 %0, t; }" : "=r"(a) : "l"(p));
    return a;
}
__device__ __forceinline__ void cp_async16(void* dst, const void* src) {
    asm volatile("cp.async.ca.shared.global [%0], [%1], 16;"
                 :: "r"(smem_u32(dst)), "l"(src) : "memory");
}
__device__ __forceinline__ void cp_commit() {
    asm volatile("cp.async.commit_group;" ::: "memory");
}
template <int NG>
__device__ __forceinline__ void cp_wait() {
    asm volatile("cp.async.wait_group %0;" :: "n"(NG) : "memory");
}

// ---------------------------------------------------------------------------
// Edge prep kernels
// ---------------------------------------------------------------------------
__global__ void k_gather2(const int* __restrict__ si, int* __restrict__ s2, int E) {
    int e = blockIdx.x * blockDim.x + threadIdx.x;
    if (e < E) {
        int a = si[e];
        s2[e] = si[a];
    }
}

__global__ void k_hist(const int* __restrict__ ti, int* __restrict__ cnt, int E) {
    int e = blockIdx.x * blockDim.x + threadIdx.x;
    if (e < E) atomicAdd(&cnt[ti[e]], 1);
}

__global__ void k_scan(const int* __restrict__ cnt, int* __restrict__ off,
                       int* __restrict__ cur, int n) {
    __shared__ int s[1024];
    int tid = threadIdx.x;
    int chunk = (n + 1023) / 1024;
    int beg = tid * chunk;
    int end = beg + chunk; if (end > n) end = n; if (beg > n) beg = n;
    int sum = 0;
    for (int i = beg; i < end; i++) sum += cnt[i];
    s[tid] = sum;
    __syncthreads();
    for (int d = 1; d < 1024; d <<= 1) {
        int v = 0;
        if (tid >= d) v = s[tid - d];
        __syncthreads();
        s[tid] += v;
        __syncthreads();
    }
    int run = s[tid] - sum;
    for (int i = beg; i < end; i++) {
        off[i] = run; cur[i] = run;
        run += cnt[i];
    }
    if (tid == 1023) off[n] = s[1023];
}

__global__ void k_scatter(const int* __restrict__ ti, const int* __restrict__ s2,
                          int* __restrict__ cur, int* __restrict__ csr,
                          int* __restrict__ rowOf, int E) {
    int e = blockIdx.x * blockDim.x + threadIdx.x;
    if (e < E) {
        int t = ti[e];
        int p = atomicAdd(&cur[t], 1);
        csr[p] = s2[e];
        rowOf[p] = t;
    }
}

__global__ void k_att(const int* __restrict__ csr, const int* __restrict__ rowOf,
                      const float* __restrict__ alpha_s, const float* __restrict__ alpha_t,
                      float* __restrict__ att, int E) {
    int j = blockIdx.x * blockDim.x + threadIdx.x;
    if (j < E) {
        float l = alpha_s[csr[j]] + alpha_t[rowOf[j]];
        l = (l > 0.f) ? l : LEAK * l;
        att[j] = __expf(l);
    }
}

// ---------------------------------------------------------------------------
// k_gemm_db: persistent, cp.async double-buffered A (in-smem tf32 convert),
//            W resident, 2 CTAs/SM. Used for L0 (64,256) and FN (128,64).
// ---------------------------------------------------------------------------
template <int K, int N, bool ALPHA, bool BIAS>
__global__ __launch_bounds__(256, 2)
void k_gemm_db(const float* __restrict__ X,
               const float* __restrict__ W0, const float* __restrict__ W1,
               const float* __restrict__ av0, const float* __restrict__ av1,
               const float* __restrict__ bias,
               float* __restrict__ Y0, float* __restrict__ Y1,
               float* __restrict__ al0, float* __restrict__ al1, int M) {
    constexpr int BM = 64;
    constexpr int KP = K + 4;
    constexpr int NP = N + 8;
    constexpr int WN = N / 4;
    constexpr int NT = WN / 8;
    constexpr int XF = BM * K / 1024;
    extern __shared__ float smf[];
    float* Wsm = smf;                     // [K][NP]
    float* A0  = smf + K * NP;            // [BM][KP] x2
    float* A1  = A0 + BM * KP;
    float* red = A1 + BM * KP;            // [BM][5]

    const int tid = threadIdx.x;
    const int wid = tid >> 5;
    const int lane = tid & 31;
    const int warpM = wid >> 2;
    const int warpN = wid & 3;
    const int q = lane >> 2;
    const int t = lane & 3;

    for (int i = tid; i < K * N / 4; i += 256) {
        int k = i / (N / 4);
        int n4 = (i % (N / 4)) * 4;
        const float* src = (N == 256)
            ? ((n4 < 128) ? (W0 + (size_t)k * 128 + n4) : (W1 + (size_t)k * 128 + (n4 - 128)))
            : (W0 + (size_t)k * N + n4);
        float4 v = *(const float4*)src;
        v.x = f2tf32(v.x); v.y = f2tf32(v.y); v.z = f2tf32(v.z); v.w = f2tf32(v.w);
        *(float4*)(Wsm + k * NP + n4) = v;
    }

    const int ntiles = (M + BM - 1) / BM;

    if ((int)blockIdx.x < ntiles) {
#pragma unroll
        for (int f = 0; f < XF; f++) {
            int i = tid + f * 256;
            int r = i / (K / 4);
            int c4 = (i % (K / 4)) * 4;
            int gr = blockIdx.x * BM + r;
            if (gr >= M) gr = M - 1;
            cp_async16(A0 + r * KP + c4, X + (size_t)gr * K + c4);
        }
    }
    cp_commit();

    int it = 0;
    for (int tile = blockIdx.x; tile < ntiles; tile += gridDim.x, it++) {
        float* curA = (it & 1) ? A1 : A0;
        float* nxtA = (it & 1) ? A0 : A1;

        int next = tile + gridDim.x;
        if (next < ntiles) {
#pragma unroll
            for (int f = 0; f < XF; f++) {
                int i = tid + f * 256;
                int r = i / (K / 4);
                int c4 = (i % (K / 4)) * 4;
                int gr = next * BM + r;
                if (gr >= M) gr = M - 1;
                cp_async16(nxtA + r * KP + c4, X + (size_t)gr * K + c4);
            }
        }
        cp_commit();
        cp_wait<1>();
#pragma unroll
        for (int f = 0; f < XF; f++) {
            int i = tid + f * 256;
            int r = i / (K / 4);
            int c4 = (i % (K / 4)) * 4;
            float4 v = *(const float4*)(curA + r * KP + c4);
            v.x = f2tf32(v.x); v.y = f2tf32(v.y); v.z = f2tf32(v.z); v.w = f2tf32(v.w);
            *(float4*)(curA + r * KP + c4) = v;
        }
        __syncthreads();

        float acc[2][NT][4];
#pragma unroll
        for (int mt = 0; mt < 2; mt++)
#pragma unroll
            for (int nt = 0; nt < NT; nt++)
#pragma unroll
                for (int j = 0; j < 4; j++) acc[mt][nt][j] = 0.f;

        const uint32_t* Au = (const uint32_t*)curA;
        const uint32_t* Bu = (const uint32_t*)Wsm;

#pragma unroll
        for (int kk = 0; kk < K; kk += 8) {
            uint32_t a[2][4];
#pragma unroll
            for (int mt = 0; mt < 2; mt++) {
                int r0 = warpM * 32 + mt * 16 + q;
                a[mt][0] = Au[r0 * KP + kk + t];
                a[mt][1] = Au[(r0 + 8) * KP + kk + t];
                a[mt][2] = Au[r0 * KP + kk + 4 + t];
                a[mt][3] = Au[(r0 + 8) * KP + kk + 4 + t];
            }
            uint32_t b[NT][2];
#pragma unroll
            for (int nt = 0; nt < NT; nt++) {
                int nc = warpN * WN + nt * 8 + q;
                b[nt][0] = Bu[(kk + t) * NP + nc];
                b[nt][1] = Bu[(kk + 4 + t) * NP + nc];
            }
#pragma unroll
            for (int mt = 0; mt < 2; mt++)
#pragma unroll
                for (int nt = 0; nt < NT; nt++) {
                    asm("mma.sync.aligned.m16n8k8.row.col.f32.tf32.tf32.f32 "
                        "{%0,%1,%2,%3}, {%4,%5,%6,%7}, {%8,%9}, {%0,%1,%2,%3};"
                        : "+f"(acc[mt][nt][0]), "+f"(acc[mt][nt][1]),
                          "+f"(acc[mt][nt][2]), "+f"(acc[mt][nt][3])
                        : "r"(a[mt][0]), "r"(a[mt][1]), "r"(a[mt][2]), "r"(a[mt][3]),
                          "r"(b[nt][0]), "r"(b[nt][1]));
                }
        }

        const int rowBase = tile * BM;
#pragma unroll
        for (int mt = 0; mt < 2; mt++) {
            int lr0 = warpM * 32 + mt * 16 + q;
            int r0 = rowBase + lr0;
            float p0 = 0.f, p1 = 0.f;
#pragma unroll
            for (int nt = 0; nt < NT; nt++) {
                int cb = warpN * WN + nt * 8 + t * 2;
                float v0 = acc[mt][nt][0], v1 = acc[mt][nt][1];
                float v2 = acc[mt][nt][2], v3 = acc[mt][nt][3];
                if (BIAS) {
                    v0 += bias[cb]; v1 += bias[cb + 1];
                    v2 += bias[cb]; v3 += bias[cb + 1];
                }
                float* Yt;
                const float* avt;
                int cc;
                if (N == 256) {
                    bool hi = cb >= 128;
                    Yt = hi ? Y1 : Y0;
                    avt = hi ? av1 : av0;
                    cc = cb & 127;
                } else {
                    Yt = Y0; avt = av0; cc = cb;
                }
                constexpr int YSTR = (N == 256) ? 128 : N;
                if (BIAS) {
                    if (r0 < M) __stcs((float2*)(Yt + (size_t)r0 * YSTR + cc), make_float2(v0, v1));
                    if (r0 + 8 < M) __stcs((float2*)(Yt + (size_t)(r0 + 8) * YSTR + cc), make_float2(v2, v3));
                } else {
                    if (r0 < M) *(float2*)(Yt + (size_t)r0 * YSTR + cc) = make_float2(v0, v1);
                    if (r0 + 8 < M) *(float2*)(Yt + (size_t)(r0 + 8) * YSTR + cc) = make_float2(v2, v3);
                }
                if (ALPHA) {
                    float a0 = avt[cc], a1 = avt[cc + 1];
                    p0 += v0 * a0 + v1 * a1;
                    p1 += v2 * a0 + v3 * a1;
                }
            }
            if (ALPHA) {
                p0 += __shfl_xor_sync(0xffffffffu, p0, 1);
                p0 += __shfl_xor_sync(0xffffffffu, p0, 2);
                p1 += __shfl_xor_sync(0xffffffffu, p1, 1);
                p1 += __shfl_xor_sync(0xffffffffu, p1, 2);
                if (t == 0) {
                    red[lr0 * 5 + warpN] = p0;
                    red[(lr0 + 8) * 5 + warpN] = p1;
                }
            }
        }
        __syncthreads();
        if (ALPHA) {
            if (tid < BM) {
                int gr = rowBase + tid;
                if (gr < M) {
                    al0[gr] = red[tid * 5 + 0] + red[tid * 5 + 1];
                    al1[gr] = red[tid * 5 + 2] + red[tid * 5 + 3];
                }
            }
            __syncthreads();
        }
    }
}

// ---------------------------------------------------------------------------
// k_gemm_l1: fused K=128,N=256 GEMM with BOTH A and W streamed in BK=32
// chunks (cp.async double-buffered). smem ~87 KB -> 2 CTAs/SM. W re-read per
// tile from L2 (131 KB resident). Dual outputs + dual fused alpha.
// ---------------------------------------------------------------------------
__global__ __launch_bounds__(256, 2)
void k_gemm_l1(const float* __restrict__ X,
               const float* __restrict__ W0, const float* __restrict__ W1,
               const float* __restrict__ av0, const float* __restrict__ av1,
               float* __restrict__ Y0, float* __restrict__ Y1,
               float* __restrict__ al0, float* __restrict__ al1, int M) {
    constexpr int K = 128;
    constexpr int N = 256;
    constexpr int BM = 64;
    constexpr int BK = 32;
    constexpr int NKB = K / BK;           // 4 chunks
    constexpr int BKP = BK + 4;           // 36
    constexpr int NP = N + 8;             // 264
    constexpr int WN = N / 4;             // 64
    constexpr int NT = WN / 8;            // 8
    extern __shared__ float smf[];
    float* B0 = smf;                       // [BK][NP] x2
    float* B1 = B0 + BK * NP;
    float* Aa0 = B1 + BK * NP;             // [BM][BKP] x2
    float* Aa1 = Aa0 + BM * BKP;
    float* red = Aa1 + BM * BKP;           // [BM][5]

    const int tid = threadIdx.x;
    const int wid = tid >> 5;
    const int lane = tid & 31;
    const int warpM = wid >> 2;
    const int warpN = wid & 3;
    const int q = lane >> 2;
    const int t = lane & 3;
    const int ntiles = (M + BM - 1) / BM;

    // chunk issue: A rows 64 x 32 cols (512 f4 -> 2/thread), W 32 x 256 (2048 f4 -> 8/thread)
    auto issue_chunk = [&](int tile, int kb, float* Ab, float* Bb) {
        int k0 = kb * BK;
#pragma unroll
        for (int f = 0; f < 2; f++) {
            int i = tid + f * 256;
            int r = i >> 3;               // /8
            int c4 = (i & 7) * 4;
            int gr = tile * BM + r;
            if (gr >= M) gr = M - 1;
            cp_async16(Ab + r * BKP + c4, X + (size_t)gr * K + k0 + c4);
        }
#pragma unroll
        for (int f = 0; f < 8; f++) {
            int i = tid + f * 256;
            int kl = i >> 6;              // /64
            int n4 = (i & 63) * 4;
            const float* src = (n4 < 128)
                ? (W0 + (size_t)(k0 + kl) * 128 + n4)
                : (W1 + (size_t)(k0 + kl) * 128 + (n4 - 128));
            cp_async16(Bb + kl * NP + n4, src);
        }
    };
    auto convert_chunk = [&](float* Ab, float* Bb) {
#pragma unroll
        for (int f = 0; f < 2; f++) {
            int i = tid + f * 256;
            int r = i >> 3;
            int c4 = (i & 7) * 4;
            float4 v = *(const float4*)(Ab + r * BKP + c4);
            v.x = f2tf32(v.x); v.y = f2tf32(v.y); v.z = f2tf32(v.z); v.w = f2tf32(v.w);
            *(float4*)(Ab + r * BKP + c4) = v;
        }
#pragma unroll
        for (int f = 0; f < 8; f++) {
            int i = tid + f * 256;
            int kl = i >> 6;
            int n4 = (i & 63) * 4;
            float4 v = *(const float4*)(Bb + kl * NP + n4);
            v.x = f2tf32(v.x); v.y = f2tf32(v.y); v.z = f2tf32(v.z); v.w = f2tf32(v.w);
            *(float4*)(Bb + kl * NP + n4) = v;
        }
    };

    // prologue: chunk 0 of first tile into buffer 0
    if ((int)blockIdx.x < ntiles) issue_chunk(blockIdx.x, 0, Aa0, B0);
    cp_commit();

    for (int tile = blockIdx.x; tile < ntiles; tile += gridDim.x) {
        float acc[2][NT][4];
#pragma unroll
        for (int mt = 0; mt < 2; mt++)
#pragma unroll
            for (int nt = 0; nt < NT; nt++)
#pragma unroll
                for (int j = 0; j < 4; j++) acc[mt][nt][j] = 0.f;

#pragma unroll
        for (int kb = 0; kb < NKB; kb++) {
            float* Ac = (kb & 1) ? Aa1 : Aa0;
            float* Bc = (kb & 1) ? B1 : B0;
            float* An = (kb & 1) ? Aa0 : Aa1;
            float* Bn = (kb & 1) ? B0 : B1;
            // issue next chunk (kb+1 of this tile, or chunk 0 of next tile)
            int nkb = kb + 1;
            int ntile = tile;
            if (nkb == NKB) { nkb = 0; ntile = tile + gridDim.x; }
            if (ntile < ntiles) issue_chunk(ntile, nkb, An, Bn);
            cp_commit();
            cp_wait<1>();          // chunk kb complete (next still in flight)
            convert_chunk(Ac, Bc);
            __syncthreads();       // converted data visible to all warps

            const uint32_t* Au = (const uint32_t*)Ac;
            const uint32_t* Bu = (const uint32_t*)Bc;
#pragma unroll
            for (int kk = 0; kk < BK; kk += 8) {
                uint32_t a[2][4];
#pragma unroll
                for (int mt = 0; mt < 2; mt++) {
                    int r0 = warpM * 32 + mt * 16 + q;
                    a[mt][0] = Au[r0 * BKP + kk + t];
                    a[mt][1] = Au[(r0 + 8) * BKP + kk + t];
                    a[mt][2] = Au[r0 * BKP + kk + 4 + t];
                    a[mt][3] = Au[(r0 + 8) * BKP + kk + 4 + t];
                }
                uint32_t b[NT][2];
#pragma unroll
                for (int nt = 0; nt < NT; nt++) {
                    int nc = warpN * WN + nt * 8 + q;
                    b[nt][0] = Bu[(kk + t) * NP + nc];
                    b[nt][1] = Bu[(kk + 4 + t) * NP + nc];
                }
#pragma unroll
                for (int mt = 0; mt < 2; mt++)
#pragma unroll
                    for (int nt = 0; nt < NT; nt++) {
                        asm("mma.sync.aligned.m16n8k8.row.col.f32.tf32.tf32.f32 "
                            "{%0,%1,%2,%3}, {%4,%5,%6,%7}, {%8,%9}, {%0,%1,%2,%3};"
                            : "+f"(acc[mt][nt][0]), "+f"(acc[mt][nt][1]),
                              "+f"(acc[mt][nt][2]), "+f"(acc[mt][nt][3])
                            : "r"(a[mt][0]), "r"(a[mt][1]), "r"(a[mt][2]), "r"(a[mt][3]),
                              "r"(b[nt][0]), "r"(b[nt][1]));
                    }
            }
            __syncthreads();   // all reads of this chunk done before overwrite
        }

        // epilogue (overlaps with in-flight load of next tile's chunk 0)
        const int rowBase = tile * BM;
#pragma unroll
        for (int mt = 0; mt < 2; mt++) {
            int lr0 = warpM * 32 + mt * 16 + q;
            int r0 = rowBase + lr0;
            float p0 = 0.f, p1 = 0.f;
#pragma unroll
            for (int nt = 0; nt < NT; nt++) {
                int cb = warpN * WN + nt * 8 + t * 2;
                float v0 = acc[mt][nt][0], v1 = acc[mt][nt][1];
                float v2 = acc[mt][nt][2], v3 = acc[mt][nt][3];
                bool hi = cb >= 128;
                float* Yt = hi ? Y1 : Y0;
                const float* avt = hi ? av1 : av0;
                int cc = cb & 127;
                if (r0 < M) *(float2*)(Yt + (size_t)r0 * 128 + cc) = make_float2(v0, v1);
                if (r0 + 8 < M) *(float2*)(Yt + (size_t)(r0 + 8) * 128 + cc) = make_float2(v2, v3);
                float a0 = avt[cc], a1 = avt[cc + 1];
                p0 += v0 * a0 + v1 * a1;
                p1 += v2 * a0 + v3 * a1;
            }
            p0 += __shfl_xor_sync(0xffffffffu, p0, 1);
            p0 += __shfl_xor_sync(0xffffffffu, p0, 2);
            p1 += __shfl_xor_sync(0xffffffffu, p1, 1);
            p1 += __shfl_xor_sync(0xffffffffu, p1, 2);
            if (t == 0) {
                red[lr0 * 5 + warpN] = p0;
                red[(lr0 + 8) * 5 + warpN] = p1;
            }
        }
        __syncthreads();
        if (tid < BM) {
            int gr = rowBase + tid;
            if (gr < M) {
                al0[gr] = red[tid * 5 + 0] + red[tid * 5 + 1];
                al1[gr] = red[tid * 5 + 2] + red[tid * 5 + 3];
            }
        }
        __syncthreads();
    }
}

// ---------------------------------------------------------------------------
// Aggregation: one warp per target node; 4+2+1 tails; streaming tgt/out.
// ---------------------------------------------------------------------------
__global__ __launch_bounds__(256)
void k_agg(const float4* __restrict__ tgt, const float4* __restrict__ src,
           const float* __restrict__ att,
           const int* __restrict__ off, const int* __restrict__ csr,
           float4* __restrict__ out, int n) {
    int w = (blockIdx.x * blockDim.x + threadIdx.x) >> 5;
    int lid = threadIdx.x & 31;
    if (w >= n) return;
    int beg = off[w];
    int end = off[w + 1];
    float4 acc = make_float4(0.f, 0.f, 0.f, 0.f);
    float den = 0.f;
    int j = beg;
    for (; j + 3 < end; j += 4) {
        int s0 = csr[j + 0], s1 = csr[j + 1], s2 = csr[j + 2], s3 = csr[j + 3];
        float a0 = att[j + 0], a1 = att[j + 1], a2 = att[j + 2], a3 = att[j + 3];
        float4 v0 = src[(size_t)s0 * 32 + lid];
        float4 v1 = src[(size_t)s1 * 32 + lid];
        float4 v2 = src[(size_t)s2 * 32 + lid];
        float4 v3 = src[(size_t)s3 * 32 + lid];
        den += (a0 + a1) + (a2 + a3);
        acc.x += a0 * v0.x + a1 * v1.x + a2 * v2.x + a3 * v3.x;
        acc.y += a0 * v0.y + a1 * v1.y + a2 * v2.y + a3 * v3.y;
        acc.z += a0 * v0.z + a1 * v1.z + a2 * v2.z + a3 * v3.z;
        acc.w += a0 * v0.w + a1 * v1.w + a2 * v2.w + a3 * v3.w;
    }
    if (j + 1 < end) {
        int s0 = csr[j + 0], s1 = csr[j + 1];
        float a0 = att[j + 0], a1 = att[j + 1];
        float4 v0 = src[(size_t)s0 * 32 + lid];
        float4 v1 = src[(size_t)s1 * 32 + lid];
        den += a0 + a1;
        acc.x += a0 * v0.x + a1 * v1.x;
        acc.y += a0 * v0.y + a1 * v1.y;
        acc.z += a0 * v0.z + a1 * v1.z;
        acc.w += a0 * v0.w + a1 * v1.w;
        j += 2;
    }
    if (j < end) {
        int s0 = csr[j];
        float a0 = att[j];
        float4 v0 = src[(size_t)s0 * 32 + lid];
        den += a0;
        acc.x += a0 * v0.x; acc.y += a0 * v0.y;
        acc.z += a0 * v0.z; acc.w += a0 * v0.w;
    }
    float inv = 1.0f / (den + EPSF);
    float4 tv = __ldcs(&tgt[(size_t)w * 32 + lid]);
    float4 r;
    r.x = fmaxf(tv.x + acc.x * inv, 0.f);
    r.y = fmaxf(tv.y + acc.y * inv, 0.f);
    r.z = fmaxf(tv.z + acc.z * inv, 0.f);
    r.w = fmaxf(tv.w + acc.w * inv, 0.f);
    __stcs(&out[(size_t)w * 32 + lid], r);
}

// ---------------------------------------------------------------------------
// Host launcher
// ---------------------------------------------------------------------------
static inline float* symf(const void* sym) {
    void* p = nullptr;
    cudaGetSymbolAddress(&p, sym);
    return (float*)p;
}
static inline int* symi(const void* sym) {
    void* p = nullptr;
    cudaGetSymbolAddress(&p, sym);
    return (int*)p;
}

extern "C" void kernel_launch(void* const* d_in, const int* in_sizes, int n_in,
                              void* d_out, int out_size) {
    const float* x_user = (const float*)d_in[0];
    const float* x_spot = (const float*)d_in[1];
    const int*   e_us   = (const int*)d_in[2];
    const int*   e_su   = (const int*)d_in[3];
    const float* Ws_us0 = (const float*)d_in[4];
    const float* Wt_us0 = (const float*)d_in[5];
    const float* a_us0  = (const float*)d_in[6];
    const float* Ws_su0 = (const float*)d_in[7];
    const float* Wt_su0 = (const float*)d_in[8];
    const float* a_su0  = (const float*)d_in[9];
    const float* Ws_us1 = (const float*)d_in[10];
    const float* Wt_us1 = (const float*)d_in[11];
    const float* a_us1  = (const float*)d_in[12];
    const float* Ws_su1 = (const float*)d_in[13];
    const float* Wt_su1 = (const float*)d_in[14];
    const float* a_su1  = (const float*)d_in[15];
    const float* W_ou   = (const float*)d_in[16];
    const float* b_ou   = (const float*)d_in[17];
    const float* W_os   = (const float*)d_in[18];
    const float* b_os   = (const float*)d_in[19];

    float* out = (float*)d_out;
    float* xu_out = out;
    float* xs_out = out + (size_t)N_USER * HID;
    float* ou_out = xs_out + (size_t)N_SPOT * HID;
    float* os_out = ou_out + (size_t)N_USER * OUTC;

    float* srcA = symf(g_srcA); float* tgtA = symf(g_tgtA);
    float* srcB = symf(g_srcB); float* tgtB = symf(g_tgtB);
    float* hu = symf(g_hu);     float* hs = symf(g_hs);
    float* alsA = symf(g_alsA); float* altA = symf(g_altA);
    float* alsB = symf(g_alsB); float* altB = symf(g_altB);
    int* si2_us = symi(g_si2_us); int* si2_su = symi(g_si2_su);
    int* cnt_us = symi(g_cnt_us); int* off_us = symi(g_off_us); int* cur_us = symi(g_cur_us);
    int* cnt_su = symi(g_cnt_su); int* off_su = symi(g_off_su); int* cur_su = symi(g_cur_su);
    int* csr_us = symi(g_csr_us); int* csr_su = symi(g_csr_su);
    int* row_us = symi(g_row_us); int* row_su = symi(g_row_su);
    float* attb = symf(g_att);

    const int EB = (EDG + 255) / 256;
    const int GP = 296;
    const int AU = (N_USER * 32 + 255) / 256;
    const int AS = (N_SPOT * 32 + 255) / 256;

    const int SM_L0 = (64 * (256 + 8) + 2 * 64 * (64 + 4) + 64 * 5) * 4;     // ~104 KB
    const int SM_L1 = (2 * 32 * (256 + 8) + 2 * 64 * (32 + 4) + 64 * 5) * 4; // ~87 KB
    const int SM_FN = (128 * (64 + 8) + 2 * 64 * (128 + 4) + 64 * 5) * 4;    // ~106 KB

    cudaFuncSetAttribute((const void*)k_gemm_db<64, 256, true, false>,
                         cudaFuncAttributeMaxDynamicSharedMemorySize, SM_L0);
    cudaFuncSetAttribute((const void*)k_gemm_l1,
                         cudaFuncAttributeMaxDynamicSharedMemorySize, SM_L1);
    cudaFuncSetAttribute((const void*)k_gemm_db<128, 64, false, true>,
                         cudaFuncAttributeMaxDynamicSharedMemorySize, SM_FN);

    // ---- prep; launch #5 = L0 DB GEMM (profiled) ----
    k_gather2<<<EB, 256>>>(e_us, si2_us, EDG);                               // 0
    k_gather2<<<EB, 256>>>(e_su, si2_su, EDG);                               // 1
    cudaMemsetAsync(cnt_us, 0, sizeof(int) * (N_SPOT + 1));                  // 2
    cudaMemsetAsync(cnt_su, 0, sizeof(int) * (N_USER + 1));                  // 3
    k_hist<<<EB, 256>>>(e_us + EDG, cnt_us, EDG);                            // 4
    k_gemm_db<64, 256, true, false><<<GP, 256, SM_L0>>>(                     // 5
        x_user, Ws_us0, Wt_su0, a_us0, a_su0 + HID, nullptr,
        srcA, tgtB, alsA, altB, N_USER);
    k_hist<<<EB, 256>>>(e_su + EDG, cnt_su, EDG);
    k_scan<<<1, 1024>>>(cnt_us, off_us, cur_us, N_SPOT);
    k_scan<<<1, 1024>>>(cnt_su, off_su, cur_su, N_USER);
    k_scatter<<<EB, 256>>>(e_us + EDG, si2_us, cur_us, csr_us, row_us, EDG);
    k_scatter<<<EB, 256>>>(e_su + EDG, si2_su, cur_su, csr_su, row_su, EDG);
    k_gemm_db<64, 256, true, false><<<GP, 256, SM_L0>>>(
        x_spot, Ws_su0, Wt_us0, a_su0, a_us0 + HID, nullptr,
        srcB, tgtA, alsB, altA, N_SPOT);

    // ---- layer 0 aggregation ----
    k_att<<<EB, 256>>>(csr_us, row_us, alsA, altA, attb, EDG);
    k_agg<<<AS, 256>>>((const float4*)tgtA, (const float4*)srcA, attb,
                       off_us, csr_us, (float4*)hs, N_SPOT);
    k_att<<<EB, 256>>>(csr_su, row_su, alsB, altB, attb, EDG);
    k_agg<<<AU, 256>>>((const float4*)tgtB, (const float4*)srcB, attb,
                       off_su, csr_su, (float4*)hu, N_USER);

    // ---- layer 1 (K=128, fused, chunk-pipelined, 2 CTAs/SM) ----
    k_gemm_l1<<<GP, 256, SM_L1>>>(
        hu, Ws_us1, Wt_su1, a_us1, a_su1 + HID,
        srcA, tgtB, alsA, altB, N_USER);
    k_gemm_l1<<<GP, 256, SM_L1>>>(
        hs, Ws_su1, Wt_us1, a_su1, a_us1 + HID,
        srcB, tgtA, alsB, altA, N_SPOT);
    k_att<<<EB, 256>>>(csr_us, row_us, alsA, altA, attb, EDG);
    k_agg<<<AS, 256>>>((const float4*)tgtA, (const float4*)srcA, attb,
                       off_us, csr_us, (float4*)xs_out, N_SPOT);
    k_att<<<EB, 256>>>(csr_su, row_su, alsB, altB, attb, EDG);
    k_agg<<<AU, 256>>>((const float4*)tgtB, (const float4*)srcB, attb,
                       off_su, csr_su, (float4*)xu_out, N_USER);

    // ---- final per-type linear (K=128, N=64, bias; DB variant) ----
    k_gemm_db<128, 64, false, true><<<GP, 256, SM_FN>>>(
        xu_out, W_ou, nullptr, nullptr, nullptr, b_ou,
        ou_out, nullptr, nullptr, nullptr, N_USER);
    k_gemm_db<128, 64, false, true><<<GP, 256, SM_FN>>>(
        xs_out, W_os, nullptr, nullptr, nullptr, b_os,
        os_out, nullptr, nullptr, nullptr, N_SPOT);
}

// round 12
// speedup vs baseline: 1.0547x; 1.0547x over previous
#include <cuda_runtime.h>
#include <cuda_bf16.h>
#include <cuda_fp16.h>
#include <cstdint>

#define N_USER 100000
#define N_SPOT 100000
#define F_IN   64
#define HID    128
#define OUTC   64
#define EDG    500000
#define LEAK   0.2f
#define EPSF   1e-6f

// ---------------------------------------------------------------------------
// Scratch (device globals; no allocation allowed)
// ---------------------------------------------------------------------------
__device__ __half g_srcAh[(size_t)N_USER * HID];   // fp16 src tables (gathered)
__device__ __half g_srcBh[(size_t)N_SPOT * HID];
__device__ float g_tgtA[(size_t)N_SPOT * HID];
__device__ float g_tgtB[(size_t)N_USER * HID];
__device__ float g_hu[(size_t)N_USER * HID];
__device__ float g_hs[(size_t)N_SPOT * HID];

__device__ float g_alsA[N_USER];
__device__ float g_altA[N_SPOT];
__device__ float g_alsB[N_SPOT];
__device__ float g_altB[N_USER];

__device__ int g_si2_us[EDG];
__device__ int g_si2_su[EDG];
__device__ int g_cnt_us[N_SPOT + 1];
__device__ int g_off_us[N_SPOT + 1];
__device__ int g_cur_us[N_SPOT + 1];
__device__ int g_cnt_su[N_USER + 1];
__device__ int g_off_su[N_USER + 1];
__device__ int g_cur_su[N_USER + 1];
__device__ int g_csr_us[EDG];
__device__ int g_csr_su[EDG];
__device__ int g_row_us[EDG];
__device__ int g_row_su[EDG];
__device__ float g_att[EDG];

__device__ __forceinline__ float f2tf32(float x) {
    float y;
    asm("cvt.rna.tf32.f32 %0, %1;" : "=f"(y) : "f"(x));
    return y;
}
__device__ __forceinline__ uint32_t smem_u32(const void* p) {
    uint32_t a;
    asm("{ .reg .u64 t; cvta.to.shared.u64 t, %1; cvt.u32.u64 %0, t; }" : "=r"(a) : "l"(p));
    return a;
}
__device__ __forceinline__ void cp_async16(void* dst, const void* src) {
    asm volatile("cp.async.ca.shared.global [%0], [%1], 16;"
                 :: "r"(smem_u32(dst)), "l"(src) : "memory");
}
__device__ __forceinline__ void cp_commit() {
    asm volatile("cp.async.commit_group;" ::: "memory");
}
template <int NG>
__device__ __forceinline__ void cp_wait() {
    asm volatile("cp.async.wait_group %0;" :: "n"(NG) : "memory");
}

// ---------------------------------------------------------------------------
// Edge prep kernels
// ---------------------------------------------------------------------------
__global__ void k_gather2(const int* __restrict__ si, int* __restrict__ s2, int E) {
    int e = blockIdx.x * blockDim.x + threadIdx.x;
    if (e < E) {
        int a = si[e];
        s2[e] = si[a];
    }
}

__global__ void k_hist(const int* __restrict__ ti, int* __restrict__ cnt, int E) {
    int e = blockIdx.x * blockDim.x + threadIdx.x;
    if (e < E) atomicAdd(&cnt[ti[e]], 1);
}

__global__ void k_scan(const int* __restrict__ cnt, int* __restrict__ off,
                       int* __restrict__ cur, int n) {
    __shared__ int s[1024];
    int tid = threadIdx.x;
    int chunk = (n + 1023) / 1024;
    int beg = tid * chunk;
    int end = beg + chunk; if (end > n) end = n; if (beg > n) beg = n;
    int sum = 0;
    for (int i = beg; i < end; i++) sum += cnt[i];
    s[tid] = sum;
    __syncthreads();
    for (int d = 1; d < 1024; d <<= 1) {
        int v = 0;
        if (tid >= d) v = s[tid - d];
        __syncthreads();
        s[tid] += v;
        __syncthreads();
    }
    int run = s[tid] - sum;
    for (int i = beg; i < end; i++) {
        off[i] = run; cur[i] = run;
        run += cnt[i];
    }
    if (tid == 1023) off[n] = s[1023];
}

__global__ void k_scatter(const int* __restrict__ ti, const int* __restrict__ s2,
                          int* __restrict__ cur, int* __restrict__ csr,
                          int* __restrict__ rowOf, int E) {
    int e = blockIdx.x * blockDim.x + threadIdx.x;
    if (e < E) {
        int t = ti[e];
        int p = atomicAdd(&cur[t], 1);
        csr[p] = s2[e];
        rowOf[p] = t;
    }
}

__global__ void k_att(const int* __restrict__ csr, const int* __restrict__ rowOf,
                      const float* __restrict__ alpha_s, const float* __restrict__ alpha_t,
                      float* __restrict__ att, int E) {
    int j = blockIdx.x * blockDim.x + threadIdx.x;
    if (j < E) {
        float l = alpha_s[csr[j]] + alpha_t[rowOf[j]];
        l = (l > 0.f) ? l : LEAK * l;
        att[j] = __expf(l);
    }
}

// ---------------------------------------------------------------------------
// Shared epilogue helper used by both GEMM kernels.
// When N==256 && H0: Y0 is an fp16 table (half2 stores), Y1 stays fp32.
// ---------------------------------------------------------------------------
template <int N, bool H0, bool BIAS>
__device__ __forceinline__ void store_pair(float* Y0, float* Y1,
                                           const float* bias,
                                           int r0, int M, int cb,
                                           float v0, float v1, float v2, float v3) {
    if (BIAS) {
        v0 += bias[cb]; v1 += bias[cb + 1];
        v2 += bias[cb]; v3 += bias[cb + 1];
    }
    if (N == 256) {
        bool hi = cb >= 128;
        int cc = cb & 127;
        if (!hi && H0) {
            __half* Yh = (__half*)Y0;
            __half2 h01 = __floats2half2_rn(v0, v1);
            __half2 h23 = __floats2half2_rn(v2, v3);
            if (r0 < M) *(__half2*)(Yh + (size_t)r0 * 128 + cc) = h01;
            if (r0 + 8 < M) *(__half2*)(Yh + (size_t)(r0 + 8) * 128 + cc) = h23;
        } else {
            float* Yt = hi ? Y1 : Y0;
            if (r0 < M) *(float2*)(Yt + (size_t)r0 * 128 + cc) = make_float2(v0, v1);
            if (r0 + 8 < M) *(float2*)(Yt + (size_t)(r0 + 8) * 128 + cc) = make_float2(v2, v3);
        }
    } else {
        if (BIAS) {
            if (r0 < M) __stcs((float2*)(Y0 + (size_t)r0 * N + cb), make_float2(v0, v1));
            if (r0 + 8 < M) __stcs((float2*)(Y0 + (size_t)(r0 + 8) * N + cb), make_float2(v2, v3));
        } else {
            if (r0 < M) *(float2*)(Y0 + (size_t)r0 * N + cb) = make_float2(v0, v1);
            if (r0 + 8 < M) *(float2*)(Y0 + (size_t)(r0 + 8) * N + cb) = make_float2(v2, v3);
        }
    }
}

// ---------------------------------------------------------------------------
// k_gemm_db: persistent, cp.async double-buffered A (in-smem tf32 convert),
//            W resident, 2 CTAs/SM. L0 (64,256,H0) and FN (128,64).
// ---------------------------------------------------------------------------
template <int K, int N, bool ALPHA, bool BIAS, bool H0>
__global__ __launch_bounds__(256, 2)
void k_gemm_db(const float* __restrict__ X,
               const float* __restrict__ W0, const float* __restrict__ W1,
               const float* __restrict__ av0, const float* __restrict__ av1,
               const float* __restrict__ bias,
               float* __restrict__ Y0, float* __restrict__ Y1,
               float* __restrict__ al0, float* __restrict__ al1, int M) {
    constexpr int BM = 64;
    constexpr int KP = K + 4;
    constexpr int NP = N + 8;
    constexpr int WN = N / 4;
    constexpr int NT = WN / 8;
    constexpr int XF = BM * K / 1024;
    extern __shared__ float smf[];
    float* Wsm = smf;                     // [K][NP]
    float* A0  = smf + K * NP;            // [BM][KP] x2
    float* A1  = A0 + BM * KP;
    float* red = A1 + BM * KP;            // [BM][5]

    const int tid = threadIdx.x;
    const int wid = tid >> 5;
    const int lane = tid & 31;
    const int warpM = wid >> 2;
    const int warpN = wid & 3;
    const int q = lane >> 2;
    const int t = lane & 3;

    for (int i = tid; i < K * N / 4; i += 256) {
        int k = i / (N / 4);
        int n4 = (i % (N / 4)) * 4;
        const float* src = (N == 256)
            ? ((n4 < 128) ? (W0 + (size_t)k * 128 + n4) : (W1 + (size_t)k * 128 + (n4 - 128)))
            : (W0 + (size_t)k * N + n4);
        float4 v = *(const float4*)src;
        v.x = f2tf32(v.x); v.y = f2tf32(v.y); v.z = f2tf32(v.z); v.w = f2tf32(v.w);
        *(float4*)(Wsm + k * NP + n4) = v;
    }

    const int ntiles = (M + BM - 1) / BM;

    if ((int)blockIdx.x < ntiles) {
#pragma unroll
        for (int f = 0; f < XF; f++) {
            int i = tid + f * 256;
            int r = i / (K / 4);
            int c4 = (i % (K / 4)) * 4;
            int gr = blockIdx.x * BM + r;
            if (gr >= M) gr = M - 1;
            cp_async16(A0 + r * KP + c4, X + (size_t)gr * K + c4);
        }
    }
    cp_commit();

    int it = 0;
    for (int tile = blockIdx.x; tile < ntiles; tile += gridDim.x, it++) {
        float* curA = (it & 1) ? A1 : A0;
        float* nxtA = (it & 1) ? A0 : A1;

        int next = tile + gridDim.x;
        if (next < ntiles) {
#pragma unroll
            for (int f = 0; f < XF; f++) {
                int i = tid + f * 256;
                int r = i / (K / 4);
                int c4 = (i % (K / 4)) * 4;
                int gr = next * BM + r;
                if (gr >= M) gr = M - 1;
                cp_async16(nxtA + r * KP + c4, X + (size_t)gr * K + c4);
            }
        }
        cp_commit();
        cp_wait<1>();
#pragma unroll
        for (int f = 0; f < XF; f++) {
            int i = tid + f * 256;
            int r = i / (K / 4);
            int c4 = (i % (K / 4)) * 4;
            float4 v = *(const float4*)(curA + r * KP + c4);
            v.x = f2tf32(v.x); v.y = f2tf32(v.y); v.z = f2tf32(v.z); v.w = f2tf32(v.w);
            *(float4*)(curA + r * KP + c4) = v;
        }
        __syncthreads();

        float acc[2][NT][4];
#pragma unroll
        for (int mt = 0; mt < 2; mt++)
#pragma unroll
            for (int nt = 0; nt < NT; nt++)
#pragma unroll
                for (int j = 0; j < 4; j++) acc[mt][nt][j] = 0.f;

        const uint32_t* Au = (const uint32_t*)curA;
        const uint32_t* Bu = (const uint32_t*)Wsm;

#pragma unroll
        for (int kk = 0; kk < K; kk += 8) {
            uint32_t a[2][4];
#pragma unroll
            for (int mt = 0; mt < 2; mt++) {
                int r0 = warpM * 32 + mt * 16 + q;
                a[mt][0] = Au[r0 * KP + kk + t];
                a[mt][1] = Au[(r0 + 8) * KP + kk + t];
                a[mt][2] = Au[r0 * KP + kk + 4 + t];
                a[mt][3] = Au[(r0 + 8) * KP + kk + 4 + t];
            }
            uint32_t b[NT][2];
#pragma unroll
            for (int nt = 0; nt < NT; nt++) {
                int nc = warpN * WN + nt * 8 + q;
                b[nt][0] = Bu[(kk + t) * NP + nc];
                b[nt][1] = Bu[(kk + 4 + t) * NP + nc];
            }
#pragma unroll
            for (int mt = 0; mt < 2; mt++)
#pragma unroll
                for (int nt = 0; nt < NT; nt++) {
                    asm("mma.sync.aligned.m16n8k8.row.col.f32.tf32.tf32.f32 "
                        "{%0,%1,%2,%3}, {%4,%5,%6,%7}, {%8,%9}, {%0,%1,%2,%3};"
                        : "+f"(acc[mt][nt][0]), "+f"(acc[mt][nt][1]),
                          "+f"(acc[mt][nt][2]), "+f"(acc[mt][nt][3])
                        : "r"(a[mt][0]), "r"(a[mt][1]), "r"(a[mt][2]), "r"(a[mt][3]),
                          "r"(b[nt][0]), "r"(b[nt][1]));
                }
        }

        const int rowBase = tile * BM;
#pragma unroll
        for (int mt = 0; mt < 2; mt++) {
            int lr0 = warpM * 32 + mt * 16 + q;
            int r0 = rowBase + lr0;
            float p0 = 0.f, p1 = 0.f;
#pragma unroll
            for (int nt = 0; nt < NT; nt++) {
                int cb = warpN * WN + nt * 8 + t * 2;
                float v0 = acc[mt][nt][0], v1 = acc[mt][nt][1];
                float v2 = acc[mt][nt][2], v3 = acc[mt][nt][3];
                store_pair<N, H0, BIAS>(Y0, Y1, bias, r0, M, cb, v0, v1, v2, v3);
                if (ALPHA) {
                    const float* avt = (N == 256 && cb >= 128) ? av1 : av0;
                    int cc = (N == 256) ? (cb & 127) : cb;
                    float a0 = avt[cc], a1 = avt[cc + 1];
                    p0 += v0 * a0 + v1 * a1;
                    p1 += v2 * a0 + v3 * a1;
                }
            }
            if (ALPHA) {
                p0 += __shfl_xor_sync(0xffffffffu, p0, 1);
                p0 += __shfl_xor_sync(0xffffffffu, p0, 2);
                p1 += __shfl_xor_sync(0xffffffffu, p1, 1);
                p1 += __shfl_xor_sync(0xffffffffu, p1, 2);
                if (t == 0) {
                    red[lr0 * 5 + warpN] = p0;
                    red[(lr0 + 8) * 5 + warpN] = p1;
                }
            }
        }
        __syncthreads();
        if (ALPHA) {
            if (tid < BM) {
                int gr = rowBase + tid;
                if (gr < M) {
                    al0[gr] = red[tid * 5 + 0] + red[tid * 5 + 1];
                    al1[gr] = red[tid * 5 + 2] + red[tid * 5 + 3];
                }
            }
            __syncthreads();
        }
    }
}

// ---------------------------------------------------------------------------
// k_gemm_pf: register-prefetch persistent GEMM (L1 fused, 170 KB smem).
// ---------------------------------------------------------------------------
template <int K, int N, bool ALPHA, bool H0>
__global__ __launch_bounds__(256)
void k_gemm_pf(const float* __restrict__ X,
               const float* __restrict__ W0, const float* __restrict__ W1,
               const float* __restrict__ av0, const float* __restrict__ av1,
               float* __restrict__ Y0, float* __restrict__ Y1,
               float* __restrict__ al0, float* __restrict__ al1, int M) {
    constexpr int KP = K + 4;
    constexpr int NP = N + 8;
    constexpr int BM = 64;
    constexpr int WN = N / 4;
    constexpr int NT = WN / 8;
    constexpr int XF = BM * K / 1024;
    extern __shared__ float smf[];
    float* Wsm = smf;
    float* As  = smf + K * NP;
    float* red = As + BM * KP;

    const int tid = threadIdx.x;
    const int wid = tid >> 5;
    const int lane = tid & 31;
    const int warpM = wid >> 2;
    const int warpN = wid & 3;
    const int q = lane >> 2;
    const int t = lane & 3;

    for (int i = tid; i < K * N / 4; i += 256) {
        int k = i / (N / 4);
        int n4 = (i % (N / 4)) * 4;
        const float* src = (n4 < 128) ? (W0 + (size_t)k * 128 + n4)
                                      : (W1 + (size_t)k * 128 + (n4 - 128));
        float4 v = *(const float4*)src;
        v.x = f2tf32(v.x); v.y = f2tf32(v.y); v.z = f2tf32(v.z); v.w = f2tf32(v.w);
        *(float4*)(Wsm + k * NP + n4) = v;
    }

    const int ntiles = (M + BM - 1) / BM;
    int tile = blockIdx.x;
    float4 xr[XF];

    if (tile < ntiles) {
#pragma unroll
        for (int f = 0; f < XF; f++) {
            int i = tid + f * 256;
            int r = i / (K / 4);
            int c4 = (i % (K / 4)) * 4;
            int gr = tile * BM + r;
            xr[f] = (gr < M) ? *(const float4*)(X + (size_t)gr * K + c4)
                             : make_float4(0.f, 0.f, 0.f, 0.f);
        }
    }
    __syncthreads();

    for (; tile < ntiles; tile += gridDim.x) {
#pragma unroll
        for (int f = 0; f < XF; f++) {
            int i = tid + f * 256;
            int r = i / (K / 4);
            int c4 = (i % (K / 4)) * 4;
            float4 v = xr[f];
            v.x = f2tf32(v.x); v.y = f2tf32(v.y); v.z = f2tf32(v.z); v.w = f2tf32(v.w);
            *(float4*)(As + r * KP + c4) = v;
        }
        __syncthreads();

        int next = tile + gridDim.x;
        if (next < ntiles) {
#pragma unroll
            for (int f = 0; f < XF; f++) {
                int i = tid + f * 256;
                int r = i / (K / 4);
                int c4 = (i % (K / 4)) * 4;
                int gr = next * BM + r;
                xr[f] = (gr < M) ? *(const float4*)(X + (size_t)gr * K + c4)
                                 : make_float4(0.f, 0.f, 0.f, 0.f);
            }
        }

        float acc[2][NT][4];
#pragma unroll
        for (int mt = 0; mt < 2; mt++)
#pragma unroll
            for (int nt = 0; nt < NT; nt++)
#pragma unroll
                for (int j = 0; j < 4; j++) acc[mt][nt][j] = 0.f;

        const uint32_t* Au = (const uint32_t*)As;
        const uint32_t* Bu = (const uint32_t*)Wsm;

#pragma unroll
        for (int kk = 0; kk < K; kk += 8) {
            uint32_t a[2][4];
#pragma unroll
            for (int mt = 0; mt < 2; mt++) {
                int r0 = warpM * 32 + mt * 16 + q;
                a[mt][0] = Au[r0 * KP + kk + t];
                a[mt][1] = Au[(r0 + 8) * KP + kk + t];
                a[mt][2] = Au[r0 * KP + kk + 4 + t];
                a[mt][3] = Au[(r0 + 8) * KP + kk + 4 + t];
            }
            uint32_t b[NT][2];
#pragma unroll
            for (int nt = 0; nt < NT; nt++) {
                int nc = warpN * WN + nt * 8 + q;
                b[nt][0] = Bu[(kk + t) * NP + nc];
                b[nt][1] = Bu[(kk + 4 + t) * NP + nc];
            }
#pragma unroll
            for (int mt = 0; mt < 2; mt++)
#pragma unroll
                for (int nt = 0; nt < NT; nt++) {
                    asm("mma.sync.aligned.m16n8k8.row.col.f32.tf32.tf32.f32 "
                        "{%0,%1,%2,%3}, {%4,%5,%6,%7}, {%8,%9}, {%0,%1,%2,%3};"
                        : "+f"(acc[mt][nt][0]), "+f"(acc[mt][nt][1]),
                          "+f"(acc[mt][nt][2]), "+f"(acc[mt][nt][3])
                        : "r"(a[mt][0]), "r"(a[mt][1]), "r"(a[mt][2]), "r"(a[mt][3]),
                          "r"(b[nt][0]), "r"(b[nt][1]));
                }
        }

        const int rowBase = tile * BM;
#pragma unroll
        for (int mt = 0; mt < 2; mt++) {
            int lr0 = warpM * 32 + mt * 16 + q;
            int r0 = rowBase + lr0;
            float p0 = 0.f, p1 = 0.f;
#pragma unroll
            for (int nt = 0; nt < NT; nt++) {
                int cb = warpN * WN + nt * 8 + t * 2;
                float v0 = acc[mt][nt][0], v1 = acc[mt][nt][1];
                float v2 = acc[mt][nt][2], v3 = acc[mt][nt][3];
                store_pair<N, H0, false>(Y0, Y1, nullptr, r0, M, cb, v0, v1, v2, v3);
                if (ALPHA) {
                    const float* avt = (cb >= 128) ? av1 : av0;
                    int cc = cb & 127;
                    float a0 = avt[cc], a1 = avt[cc + 1];
                    p0 += v0 * a0 + v1 * a1;
                    p1 += v2 * a0 + v3 * a1;
                }
            }
            if (ALPHA) {
                p0 += __shfl_xor_sync(0xffffffffu, p0, 1);
                p0 += __shfl_xor_sync(0xffffffffu, p0, 2);
                p1 += __shfl_xor_sync(0xffffffffu, p1, 1);
                p1 += __shfl_xor_sync(0xffffffffu, p1, 2);
                if (t == 0) {
                    red[lr0 * 5 + warpN] = p0;
                    red[(lr0 + 8) * 5 + warpN] = p1;
                }
            }
        }
        __syncthreads();
        if (ALPHA) {
            if (tid < BM) {
                int gr = rowBase + tid;
                if (gr < M) {
                    al0[gr] = red[tid * 5 + 0] + red[tid * 5 + 1];
                    al1[gr] = red[tid * 5 + 2] + red[tid * 5 + 3];
                }
            }
            __syncthreads();
        }
    }
}

// ---------------------------------------------------------------------------
// Aggregation: one warp per target node; src table is fp16 (uint2 = 4 halves
// per lane). 4+2+1 tails; streaming tgt/out.
// ---------------------------------------------------------------------------
__device__ __forceinline__ void acc_row(float4& acc, float a, uint2 u) {
    __half2 h0 = *(__half2*)&u.x;
    __half2 h1 = *(__half2*)&u.y;
    float2 f0 = __half22float2(h0);
    float2 f1 = __half22float2(h1);
    acc.x += a * f0.x; acc.y += a * f0.y;
    acc.z += a * f1.x; acc.w += a * f1.y;
}

__global__ __launch_bounds__(256)
void k_agg(const float4* __restrict__ tgt, const uint2* __restrict__ src,
           const float* __restrict__ att,
           const int* __restrict__ off, const int* __restrict__ csr,
           float4* __restrict__ out, int n) {
    int w = (blockIdx.x * blockDim.x + threadIdx.x) >> 5;
    int lid = threadIdx.x & 31;
    if (w >= n) return;
    int beg = off[w];
    int end = off[w + 1];
    float4 acc = make_float4(0.f, 0.f, 0.f, 0.f);
    float den = 0.f;
    int j = beg;
    for (; j + 3 < end; j += 4) {
        int s0 = csr[j + 0], s1 = csr[j + 1], s2 = csr[j + 2], s3 = csr[j + 3];
        float a0 = att[j + 0], a1 = att[j + 1], a2 = att[j + 2], a3 = att[j + 3];
        uint2 u0 = src[(size_t)s0 * 32 + lid];
        uint2 u1 = src[(size_t)s1 * 32 + lid];
        uint2 u2 = src[(size_t)s2 * 32 + lid];
        uint2 u3 = src[(size_t)s3 * 32 + lid];
        den += (a0 + a1) + (a2 + a3);
        acc_row(acc, a0, u0);
        acc_row(acc, a1, u1);
        acc_row(acc, a2, u2);
        acc_row(acc, a3, u3);
    }
    if (j + 1 < end) {
        int s0 = csr[j + 0], s1 = csr[j + 1];
        float a0 = att[j + 0], a1 = att[j + 1];
        uint2 u0 = src[(size_t)s0 * 32 + lid];
        uint2 u1 = src[(size_t)s1 * 32 + lid];
        den += a0 + a1;
        acc_row(acc, a0, u0);
        acc_row(acc, a1, u1);
        j += 2;
    }
    if (j < end) {
        int s0 = csr[j];
        float a0 = att[j];
        uint2 u0 = src[(size_t)s0 * 32 + lid];
        den += a0;
        acc_row(acc, a0, u0);
    }
    float inv = 1.0f / (den + EPSF);
    float4 tv = __ldcs(&tgt[(size_t)w * 32 + lid]);
    float4 r;
    r.x = fmaxf(tv.x + acc.x * inv, 0.f);
    r.y = fmaxf(tv.y + acc.y * inv, 0.f);
    r.z = fmaxf(tv.z + acc.z * inv, 0.f);
    r.w = fmaxf(tv.w + acc.w * inv, 0.f);
    __stcs(&out[(size_t)w * 32 + lid], r);
}

// ---------------------------------------------------------------------------
// Host launcher
// ---------------------------------------------------------------------------
static inline float* symf(const void* sym) {
    void* p = nullptr;
    cudaGetSymbolAddress(&p, sym);
    return (float*)p;
}
static inline int* symi(const void* sym) {
    void* p = nullptr;
    cudaGetSymbolAddress(&p, sym);
    return (int*)p;
}

extern "C" void kernel_launch(void* const* d_in, const int* in_sizes, int n_in,
                              void* d_out, int out_size) {
    const float* x_user = (const float*)d_in[0];
    const float* x_spot = (const float*)d_in[1];
    const int*   e_us   = (const int*)d_in[2];
    const int*   e_su   = (const int*)d_in[3];
    const float* Ws_us0 = (const float*)d_in[4];
    const float* Wt_us0 = (const float*)d_in[5];
    const float* a_us0  = (const float*)d_in[6];
    const float* Ws_su0 = (const float*)d_in[7];
    const float* Wt_su0 = (const float*)d_in[8];
    const float* a_su0  = (const float*)d_in[9];
    const float* Ws_us1 = (const float*)d_in[10];
    const float* Wt_us1 = (const float*)d_in[11];
    const float* a_us1  = (const float*)d_in[12];
    const float* Ws_su1 = (const float*)d_in[13];
    const float* Wt_su1 = (const float*)d_in[14];
    const float* a_su1  = (const float*)d_in[15];
    const float* W_ou   = (const float*)d_in[16];
    const float* b_ou   = (const float*)d_in[17];
    const float* W_os   = (const float*)d_in[18];
    const float* b_os   = (const float*)d_in[19];

    float* out = (float*)d_out;
    float* xu_out = out;
    float* xs_out = out + (size_t)N_USER * HID;
    float* ou_out = xs_out + (size_t)N_SPOT * HID;
    float* os_out = ou_out + (size_t)N_USER * OUTC;

    float* srcAh = symf(g_srcAh);   // __half, cast as float* for kernel param
    float* srcBh = symf(g_srcBh);
    float* tgtA = symf(g_tgtA); float* tgtB = symf(g_tgtB);
    float* hu = symf(g_hu);     float* hs = symf(g_hs);
    float* alsA = symf(g_alsA); float* altA = symf(g_altA);
    float* alsB = symf(g_alsB); float* altB = symf(g_altB);
    int* si2_us = symi(g_si2_us); int* si2_su = symi(g_si2_su);
    int* cnt_us = symi(g_cnt_us); int* off_us = symi(g_off_us); int* cur_us = symi(g_cur_us);
    int* cnt_su = symi(g_cnt_su); int* off_su = symi(g_off_su); int* cur_su = symi(g_cur_su);
    int* csr_us = symi(g_csr_us); int* csr_su = symi(g_csr_su);
    int* row_us = symi(g_row_us); int* row_su = symi(g_row_su);
    float* attb = symf(g_att);

    const int EB = (EDG + 255) / 256;
    const int GP = 296;
    const int GP1 = 148;
    const int AU = (N_USER * 32 + 255) / 256;
    const int AS = (N_SPOT * 32 + 255) / 256;

    const int SM_L0 = (64 * (256 + 8) + 2 * 64 * (64 + 4) + 64 * 5) * 4;     // ~104 KB
    const int SM_L1 = (128 * (256 + 8) + 64 * (128 + 4) + 64 * 5) * 4;       // ~170 KB
    const int SM_FN = (128 * (64 + 8) + 2 * 64 * (128 + 4) + 64 * 5) * 4;    // ~106 KB

    cudaFuncSetAttribute((const void*)k_gemm_db<64, 256, true, false, true>,
                         cudaFuncAttributeMaxDynamicSharedMemorySize, SM_L0);
    cudaFuncSetAttribute((const void*)k_gemm_pf<128, 256, true, true>,
                         cudaFuncAttributeMaxDynamicSharedMemorySize, SM_L1);
    cudaFuncSetAttribute((const void*)k_gemm_db<128, 64, false, true, false>,
                         cudaFuncAttributeMaxDynamicSharedMemorySize, SM_FN);

    // ---- prep; launch #5 = L0 DB GEMM (profiled) ----
    k_gather2<<<EB, 256>>>(e_us, si2_us, EDG);                               // 0
    k_gather2<<<EB, 256>>>(e_su, si2_su, EDG);                               // 1
    cudaMemsetAsync(cnt_us, 0, sizeof(int) * (N_SPOT + 1));                  // 2
    cudaMemsetAsync(cnt_su, 0, sizeof(int) * (N_USER + 1));                  // 3
    k_hist<<<EB, 256>>>(e_us + EDG, cnt_us, EDG);                            // 4
    // x_user -> [srcA(fp16) | tgtB], alphas [alsA | altB]
    k_gemm_db<64, 256, true, false, true><<<GP, 256, SM_L0>>>(               // 5
        x_user, Ws_us0, Wt_su0, a_us0, a_su0 + HID, nullptr,
        srcAh, tgtB, alsA, altB, N_USER);
    k_hist<<<EB, 256>>>(e_su + EDG, cnt_su, EDG);
    k_scan<<<1, 1024>>>(cnt_us, off_us, cur_us, N_SPOT);
    k_scan<<<1, 1024>>>(cnt_su, off_su, cur_su, N_USER);
    k_scatter<<<EB, 256>>>(e_us + EDG, si2_us, cur_us, csr_us, row_us, EDG);
    k_scatter<<<EB, 256>>>(e_su + EDG, si2_su, cur_su, csr_su, row_su, EDG);
    // x_spot -> [srcB(fp16) | tgtA], alphas [alsB | altA]
    k_gemm_db<64, 256, true, false, true><<<GP, 256, SM_L0>>>(
        x_spot, Ws_su0, Wt_us0, a_su0, a_us0 + HID, nullptr,
        srcBh, tgtA, alsB, altA, N_SPOT);

    // ---- layer 0 aggregation ----
    k_att<<<EB, 256>>>(csr_us, row_us, alsA, altA, attb, EDG);
    k_agg<<<AS, 256>>>((const float4*)tgtA, (const uint2*)srcAh, attb,
                       off_us, csr_us, (float4*)hs, N_SPOT);
    k_att<<<EB, 256>>>(csr_su, row_su, alsB, altB, attb, EDG);
    k_agg<<<AU, 256>>>((const float4*)tgtB, (const uint2*)srcBh, attb,
                       off_su, csr_su, (float4*)hu, N_USER);

    // ---- layer 1 (K=128, fused, register-prefetch variant) ----
    k_gemm_pf<128, 256, true, true><<<GP1, 256, SM_L1>>>(
        hu, Ws_us1, Wt_su1, a_us1, a_su1 + HID,
        srcAh, tgtB, alsA, altB, N_USER);
    k_gemm_pf<128, 256, true, true><<<GP1, 256, SM_L1>>>(
        hs, Ws_su1, Wt_us1, a_su1, a_us1 + HID,
        srcBh, tgtA, alsB, altA, N_SPOT);
    k_att<<<EB, 256>>>(csr_us, row_us, alsA, altA, attb, EDG);
    k_agg<<<AS, 256>>>((const float4*)tgtA, (const uint2*)srcAh, attb,
                       off_us, csr_us, (float4*)xs_out, N_SPOT);
    k_att<<<EB, 256>>>(csr_su, row_su, alsB, altB, attb, EDG);
    k_agg<<<AU, 256>>>((const float4*)tgtB, (const uint2*)srcBh, attb,
                       off_su, csr_su, (float4*)xu_out, N_USER);

    // ---- final per-type linear (K=128, N=64, bias; DB variant) ----
    k_gemm_db<128, 64, false, true, false><<<GP, 256, SM_FN>>>(
        xu_out, W_ou, nullptr, nullptr, nullptr, b_ou,
        ou_out, nullptr, nullptr, nullptr, N_USER);
    k_gemm_db<128, 64, false, true, false><<<GP, 256, SM_FN>>>(
        xs_out, W_os, nullptr, nullptr, nullptr, b_os,
        os_out, nullptr, nullptr, nullptr, N_SPOT);
}

// round 13
// speedup vs baseline: 1.0730x; 1.0173x over previous
#include <cuda_runtime.h>
#include <cuda_bf16.h>
#include <cuda_fp16.h>
#include <cstdint>

#define N_USER 100000
#define N_SPOT 100000
#define F_IN   64
#define HID    128
#define OUTC   64
#define EDG    500000
#define LEAK   0.2f
#define EPSF   1e-6f

// ---------------------------------------------------------------------------
// Scratch (device globals; no allocation allowed)
// ---------------------------------------------------------------------------
__device__ __half g_srcAh[(size_t)N_USER * HID];   // fp16 src tables (gathered)
__device__ __half g_srcBh[(size_t)N_SPOT * HID];
__device__ float g_tgtA[(size_t)N_SPOT * HID];
__device__ float g_tgtB[(size_t)N_USER * HID];
__device__ float g_hu[(size_t)N_USER * HID];
__device__ float g_hs[(size_t)N_SPOT * HID];

__device__ float g_alsA[N_USER];
__device__ float g_altA[N_SPOT];
__device__ float g_alsB[N_SPOT];
__device__ float g_altB[N_USER];

__device__ int g_si2_us[EDG];
__device__ int g_si2_su[EDG];
__device__ int g_cnt_us[N_SPOT + 1];
__device__ int g_off_us[N_SPOT + 1];
__device__ int g_cur_us[N_SPOT + 1];
__device__ int g_cnt_su[N_USER + 1];
__device__ int g_off_su[N_USER + 1];
__device__ int g_cur_su[N_USER + 1];
__device__ int g_csr_us[EDG];
__device__ int g_csr_su[EDG];
__device__ int g_row_us[EDG];
__device__ int g_row_su[EDG];
__device__ float g_att[EDG];

__device__ __forceinline__ float f2tf32(float x) {
    float y;
    asm("cvt.rna.tf32.f32 %0, %1;" : "=f"(y) : "f"(x));
    return y;
}
__device__ __forceinline__ uint32_t smem_u32(const void* p) {
    uint32_t a;
    asm("{ .reg .u64 t; cvta.to.shared.u64 t, %1; cvt.u32.u64 %0, t; }" : "=r"(a) : "l"(p));
    return a;
}
__device__ __forceinline__ void cp_async16(void* dst, const void* src) {
    asm volatile("cp.async.ca.shared.global [%0], [%1], 16;"
                 :: "r"(smem_u32(dst)), "l"(src) : "memory");
}
__device__ __forceinline__ void cp_commit() {
    asm volatile("cp.async.commit_group;" ::: "memory");
}
template <int NG>
__device__ __forceinline__ void cp_wait() {
    asm volatile("cp.async.wait_group %0;" :: "n"(NG) : "memory");
}

// ---------------------------------------------------------------------------
// Edge prep kernels
// ---------------------------------------------------------------------------
__global__ void k_gather2(const int* __restrict__ si, int* __restrict__ s2, int E) {
    int e = blockIdx.x * blockDim.x + threadIdx.x;
    if (e < E) {
        int a = si[e];
        s2[e] = si[a];
    }
}

__global__ void k_hist(const int* __restrict__ ti, int* __restrict__ cnt, int E) {
    int e = blockIdx.x * blockDim.x + threadIdx.x;
    if (e < E) atomicAdd(&cnt[ti[e]], 1);
}

__global__ void k_scan(const int* __restrict__ cnt, int* __restrict__ off,
                       int* __restrict__ cur, int n) {
    __shared__ int s[1024];
    int tid = threadIdx.x;
    int chunk = (n + 1023) / 1024;
    int beg = tid * chunk;
    int end = beg + chunk; if (end > n) end = n; if (beg > n) beg = n;
    int sum = 0;
    for (int i = beg; i < end; i++) sum += cnt[i];
    s[tid] = sum;
    __syncthreads();
    for (int d = 1; d < 1024; d <<= 1) {
        int v = 0;
        if (tid >= d) v = s[tid - d];
        __syncthreads();
        s[tid] += v;
        __syncthreads();
    }
    int run = s[tid] - sum;
    for (int i = beg; i < end; i++) {
        off[i] = run; cur[i] = run;
        run += cnt[i];
    }
    if (tid == 1023) off[n] = s[1023];
}

__global__ void k_scatter(const int* __restrict__ ti, const int* __restrict__ s2,
                          int* __restrict__ cur, int* __restrict__ csr,
                          int* __restrict__ rowOf, int E) {
    int e = blockIdx.x * blockDim.x + threadIdx.x;
    if (e < E) {
        int t = ti[e];
        int p = atomicAdd(&cur[t], 1);
        csr[p] = s2[e];
        rowOf[p] = t;
    }
}

__global__ void k_att(const int* __restrict__ csr, const int* __restrict__ rowOf,
                      const float* __restrict__ alpha_s, const float* __restrict__ alpha_t,
                      float* __restrict__ att, int E) {
    int j = blockIdx.x * blockDim.x + threadIdx.x;
    if (j < E) {
        float l = alpha_s[csr[j]] + alpha_t[rowOf[j]];
        l = (l > 0.f) ? l : LEAK * l;
        att[j] = __expf(l);
    }
}

// ---------------------------------------------------------------------------
// Shared epilogue store helper.
// When N==256 && H0: Y0 is an fp16 table (half2 stores), Y1 stays fp32.
// ---------------------------------------------------------------------------
template <int N, bool H0, bool BIAS>
__device__ __forceinline__ void store_pair(float* Y0, float* Y1,
                                           const float* bias,
                                           int r0, int M, int cb,
                                           float v0, float v1, float v2, float v3) {
    if (BIAS) {
        v0 += bias[cb]; v1 += bias[cb + 1];
        v2 += bias[cb]; v3 += bias[cb + 1];
    }
    if (N == 256) {
        bool hi = cb >= 128;
        int cc = cb & 127;
        if (!hi && H0) {
            __half* Yh = (__half*)Y0;
            __half2 h01 = __floats2half2_rn(v0, v1);
            __half2 h23 = __floats2half2_rn(v2, v3);
            if (r0 < M) *(__half2*)(Yh + (size_t)r0 * 128 + cc) = h01;
            if (r0 + 8 < M) *(__half2*)(Yh + (size_t)(r0 + 8) * 128 + cc) = h23;
        } else {
            float* Yt = hi ? Y1 : Y0;
            if (r0 < M) *(float2*)(Yt + (size_t)r0 * 128 + cc) = make_float2(v0, v1);
            if (r0 + 8 < M) *(float2*)(Yt + (size_t)(r0 + 8) * 128 + cc) = make_float2(v2, v3);
        }
    } else {
        if (BIAS) {
            if (r0 < M) __stcs((float2*)(Y0 + (size_t)r0 * N + cb), make_float2(v0, v1));
            if (r0 + 8 < M) __stcs((float2*)(Y0 + (size_t)(r0 + 8) * N + cb), make_float2(v2, v3));
        } else {
            if (r0 < M) *(float2*)(Y0 + (size_t)r0 * N + cb) = make_float2(v0, v1);
            if (r0 + 8 < M) *(float2*)(Y0 + (size_t)(r0 + 8) * N + cb) = make_float2(v2, v3);
        }
    }
}

// ---------------------------------------------------------------------------
// k_gemm_db: persistent, cp.async double-buffered A (in-smem tf32 convert),
//            W resident, 2 CTAs/SM. L0 (64,256,H0) and FN (128,64).
// ---------------------------------------------------------------------------
template <int K, int N, bool ALPHA, bool BIAS, bool H0>
__global__ __launch_bounds__(256, 2)
void k_gemm_db(const float* __restrict__ X,
               const float* __restrict__ W0, const float* __restrict__ W1,
               const float* __restrict__ av0, const float* __restrict__ av1,
               const float* __restrict__ bias,
               float* __restrict__ Y0, float* __restrict__ Y1,
               float* __restrict__ al0, float* __restrict__ al1, int M) {
    constexpr int BM = 64;
    constexpr int KP = K + 4;
    constexpr int NP = N + 8;
    constexpr int WN = N / 4;
    constexpr int NT = WN / 8;
    constexpr int XF = BM * K / 1024;
    extern __shared__ float smf[];
    float* Wsm = smf;                     // [K][NP]
    float* A0  = smf + K * NP;            // [BM][KP] x2
    float* A1  = A0 + BM * KP;
    float* red = A1 + BM * KP;            // [BM][5]

    const int tid = threadIdx.x;
    const int wid = tid >> 5;
    const int lane = tid & 31;
    const int warpM = wid >> 2;
    const int warpN = wid & 3;
    const int q = lane >> 2;
    const int t = lane & 3;

    for (int i = tid; i < K * N / 4; i += 256) {
        int k = i / (N / 4);
        int n4 = (i % (N / 4)) * 4;
        const float* src = (N == 256)
            ? ((n4 < 128) ? (W0 + (size_t)k * 128 + n4) : (W1 + (size_t)k * 128 + (n4 - 128)))
            : (W0 + (size_t)k * N + n4);
        float4 v = *(const float4*)src;
        v.x = f2tf32(v.x); v.y = f2tf32(v.y); v.z = f2tf32(v.z); v.w = f2tf32(v.w);
        *(float4*)(Wsm + k * NP + n4) = v;
    }

    const int ntiles = (M + BM - 1) / BM;

    if ((int)blockIdx.x < ntiles) {
#pragma unroll
        for (int f = 0; f < XF; f++) {
            int i = tid + f * 256;
            int r = i / (K / 4);
            int c4 = (i % (K / 4)) * 4;
            int gr = blockIdx.x * BM + r;
            if (gr >= M) gr = M - 1;
            cp_async16(A0 + r * KP + c4, X + (size_t)gr * K + c4);
        }
    }
    cp_commit();

    int it = 0;
    for (int tile = blockIdx.x; tile < ntiles; tile += gridDim.x, it++) {
        float* curA = (it & 1) ? A1 : A0;
        float* nxtA = (it & 1) ? A0 : A1;

        int next = tile + gridDim.x;
        if (next < ntiles) {
#pragma unroll
            for (int f = 0; f < XF; f++) {
                int i = tid + f * 256;
                int r = i / (K / 4);
                int c4 = (i % (K / 4)) * 4;
                int gr = next * BM + r;
                if (gr >= M) gr = M - 1;
                cp_async16(nxtA + r * KP + c4, X + (size_t)gr * K + c4);
            }
        }
        cp_commit();
        cp_wait<1>();
#pragma unroll
        for (int f = 0; f < XF; f++) {
            int i = tid + f * 256;
            int r = i / (K / 4);
            int c4 = (i % (K / 4)) * 4;
            float4 v = *(const float4*)(curA + r * KP + c4);
            v.x = f2tf32(v.x); v.y = f2tf32(v.y); v.z = f2tf32(v.z); v.w = f2tf32(v.w);
            *(float4*)(curA + r * KP + c4) = v;
        }
        __syncthreads();

        float acc[2][NT][4];
#pragma unroll
        for (int mt = 0; mt < 2; mt++)
#pragma unroll
            for (int nt = 0; nt < NT; nt++)
#pragma unroll
                for (int j = 0; j < 4; j++) acc[mt][nt][j] = 0.f;

        const uint32_t* Au = (const uint32_t*)curA;
        const uint32_t* Bu = (const uint32_t*)Wsm;

#pragma unroll
        for (int kk = 0; kk < K; kk += 8) {
            uint32_t a[2][4];
#pragma unroll
            for (int mt = 0; mt < 2; mt++) {
                int r0 = warpM * 32 + mt * 16 + q;
                a[mt][0] = Au[r0 * KP + kk + t];
                a[mt][1] = Au[(r0 + 8) * KP + kk + t];
                a[mt][2] = Au[r0 * KP + kk + 4 + t];
                a[mt][3] = Au[(r0 + 8) * KP + kk + 4 + t];
            }
            uint32_t b[NT][2];
#pragma unroll
            for (int nt = 0; nt < NT; nt++) {
                int nc = warpN * WN + nt * 8 + q;
                b[nt][0] = Bu[(kk + t) * NP + nc];
                b[nt][1] = Bu[(kk + 4 + t) * NP + nc];
            }
#pragma unroll
            for (int mt = 0; mt < 2; mt++)
#pragma unroll
                for (int nt = 0; nt < NT; nt++) {
                    asm("mma.sync.aligned.m16n8k8.row.col.f32.tf32.tf32.f32 "
                        "{%0,%1,%2,%3}, {%4,%5,%6,%7}, {%8,%9}, {%0,%1,%2,%3};"
                        : "+f"(acc[mt][nt][0]), "+f"(acc[mt][nt][1]),
                          "+f"(acc[mt][nt][2]), "+f"(acc[mt][nt][3])
                        : "r"(a[mt][0]), "r"(a[mt][1]), "r"(a[mt][2]), "r"(a[mt][3]),
                          "r"(b[nt][0]), "r"(b[nt][1]));
                }
        }

        const int rowBase = tile * BM;
#pragma unroll
        for (int mt = 0; mt < 2; mt++) {
            int lr0 = warpM * 32 + mt * 16 + q;
            int r0 = rowBase + lr0;
            float p0 = 0.f, p1 = 0.f;
#pragma unroll
            for (int nt = 0; nt < NT; nt++) {
                int cb = warpN * WN + nt * 8 + t * 2;
                float v0 = acc[mt][nt][0], v1 = acc[mt][nt][1];
                float v2 = acc[mt][nt][2], v3 = acc[mt][nt][3];
                store_pair<N, H0, BIAS>(Y0, Y1, bias, r0, M, cb, v0, v1, v2, v3);
                if (ALPHA) {
                    const float* avt = (N == 256 && cb >= 128) ? av1 : av0;
                    int cc = (N == 256) ? (cb & 127) : cb;
                    float a0 = avt[cc], a1 = avt[cc + 1];
                    p0 += v0 * a0 + v1 * a1;
                    p1 += v2 * a0 + v3 * a1;
                }
            }
            if (ALPHA) {
                p0 += __shfl_xor_sync(0xffffffffu, p0, 1);
                p0 += __shfl_xor_sync(0xffffffffu, p0, 2);
                p1 += __shfl_xor_sync(0xffffffffu, p1, 1);
                p1 += __shfl_xor_sync(0xffffffffu, p1, 2);
                if (t == 0) {
                    red[lr0 * 5 + warpN] = p0;
                    red[(lr0 + 8) * 5 + warpN] = p1;
                }
            }
        }
        __syncthreads();
        if (ALPHA) {
            if (tid < BM) {
                int gr = rowBase + tid;
                if (gr < M) {
                    al0[gr] = red[tid * 5 + 0] + red[tid * 5 + 1];
                    al1[gr] = red[tid * 5 + 2] + red[tid * 5 + 3];
                }
            }
            __syncthreads();
        }
    }
}

// ---------------------------------------------------------------------------
// k_gemm_l1: fused L1 GEMM (K=128, N=256) with 512 threads = 16 warps
// (2M x 8N, warp tile 32x32, NT=4). W resident, register-prefetch A.
// smem ~171 KB -> 1 CTA/SM but 16 warps (2x the pf variant's latency hiding).
// Y0 = fp16 table; dual fused alpha.
// ---------------------------------------------------------------------------
__global__ __launch_bounds__(512, 1)
void k_gemm_l1(const float* __restrict__ X,
               const float* __restrict__ W0, const float* __restrict__ W1,
               const float* __restrict__ av0, const float* __restrict__ av1,
               float* __restrict__ Y0, float* __restrict__ Y1,
               float* __restrict__ al0, float* __restrict__ al1, int M) {
    constexpr int K = 128;
    constexpr int N = 256;
    constexpr int BM = 64;
    constexpr int KP = K + 4;     // 132
    constexpr int NP = N + 8;     // 264
    constexpr int WN = 32;
    constexpr int NT = 4;
    constexpr int XF = BM * K / (512 * 4);   // 4 float4 per thread
    extern __shared__ float smf[];
    float* Wsm = smf;                 // [K][NP]
    float* As  = smf + K * NP;        // [BM][KP]
    float* red = As + BM * KP;        // [BM][9]

    const int tid = threadIdx.x;
    const int wid = tid >> 5;
    const int lane = tid & 31;
    const int warpM = wid >> 3;       // 0..1
    const int warpN = wid & 7;        // 0..7
    const int q = lane >> 2;
    const int t = lane & 3;

    // stage W once
    for (int i = tid; i < K * N / 4; i += 512) {
        int k = i / (N / 4);
        int n4 = (i % (N / 4)) * 4;
        const float* src = (n4 < 128) ? (W0 + (size_t)k * 128 + n4)
                                      : (W1 + (size_t)k * 128 + (n4 - 128));
        float4 v = *(const float4*)src;
        v.x = f2tf32(v.x); v.y = f2tf32(v.y); v.z = f2tf32(v.z); v.w = f2tf32(v.w);
        *(float4*)(Wsm + k * NP + n4) = v;
    }

    const int ntiles = (M + BM - 1) / BM;
    int tile = blockIdx.x;
    float4 xr[XF];

    if (tile < ntiles) {
#pragma unroll
        for (int f = 0; f < XF; f++) {
            int i = tid + f * 512;
            int r = i >> 5;               // / (K/4)=32
            int c4 = (i & 31) * 4;
            int gr = tile * BM + r;
            xr[f] = (gr < M) ? *(const float4*)(X + (size_t)gr * K + c4)
                             : make_float4(0.f, 0.f, 0.f, 0.f);
        }
    }
    __syncthreads();   // W staged

    for (; tile < ntiles; tile += gridDim.x) {
#pragma unroll
        for (int f = 0; f < XF; f++) {
            int i = tid + f * 512;
            int r = i >> 5;
            int c4 = (i & 31) * 4;
            float4 v = xr[f];
            v.x = f2tf32(v.x); v.y = f2tf32(v.y); v.z = f2tf32(v.z); v.w = f2tf32(v.w);
            *(float4*)(As + r * KP + c4) = v;
        }
        __syncthreads();

        int next = tile + gridDim.x;
        if (next < ntiles) {
#pragma unroll
            for (int f = 0; f < XF; f++) {
                int i = tid + f * 512;
                int r = i >> 5;
                int c4 = (i & 31) * 4;
                int gr = next * BM + r;
                xr[f] = (gr < M) ? *(const float4*)(X + (size_t)gr * K + c4)
                                 : make_float4(0.f, 0.f, 0.f, 0.f);
            }
        }

        float acc[2][NT][4];
#pragma unroll
        for (int mt = 0; mt < 2; mt++)
#pragma unroll
            for (int nt = 0; nt < NT; nt++)
#pragma unroll
                for (int j = 0; j < 4; j++) acc[mt][nt][j] = 0.f;

        const uint32_t* Au = (const uint32_t*)As;
        const uint32_t* Bu = (const uint32_t*)Wsm;

#pragma unroll
        for (int kk = 0; kk < K; kk += 8) {
            uint32_t a[2][4];
#pragma unroll
            for (int mt = 0; mt < 2; mt++) {
                int r0 = warpM * 32 + mt * 16 + q;
                a[mt][0] = Au[r0 * KP + kk + t];
                a[mt][1] = Au[(r0 + 8) * KP + kk + t];
                a[mt][2] = Au[r0 * KP + kk + 4 + t];
                a[mt][3] = Au[(r0 + 8) * KP + kk + 4 + t];
            }
            uint32_t b[NT][2];
#pragma unroll
            for (int nt = 0; nt < NT; nt++) {
                int nc = warpN * WN + nt * 8 + q;
                b[nt][0] = Bu[(kk + t) * NP + nc];
                b[nt][1] = Bu[(kk + 4 + t) * NP + nc];
            }
#pragma unroll
            for (int mt = 0; mt < 2; mt++)
#pragma unroll
                for (int nt = 0; nt < NT; nt++) {
                    asm("mma.sync.aligned.m16n8k8.row.col.f32.tf32.tf32.f32 "
                        "{%0,%1,%2,%3}, {%4,%5,%6,%7}, {%8,%9}, {%0,%1,%2,%3};"
                        : "+f"(acc[mt][nt][0]), "+f"(acc[mt][nt][1]),
                          "+f"(acc[mt][nt][2]), "+f"(acc[mt][nt][3])
                        : "r"(a[mt][0]), "r"(a[mt][1]), "r"(a[mt][2]), "r"(a[mt][3]),
                          "r"(b[nt][0]), "r"(b[nt][1]));
                }
        }

        const int rowBase = tile * BM;
#pragma unroll
        for (int mt = 0; mt < 2; mt++) {
            int lr0 = warpM * 32 + mt * 16 + q;
            int r0 = rowBase + lr0;
            float p0 = 0.f, p1 = 0.f;
#pragma unroll
            for (int nt = 0; nt < NT; nt++) {
                int cb = warpN * WN + nt * 8 + t * 2;
                float v0 = acc[mt][nt][0], v1 = acc[mt][nt][1];
                float v2 = acc[mt][nt][2], v3 = acc[mt][nt][3];
                store_pair<256, true, false>(Y0, Y1, nullptr, r0, M, cb, v0, v1, v2, v3);
                const float* avt = (cb >= 128) ? av1 : av0;
                int cc = cb & 127;
                float a0 = avt[cc], a1 = avt[cc + 1];
                p0 += v0 * a0 + v1 * a1;
                p1 += v2 * a0 + v3 * a1;
            }
            p0 += __shfl_xor_sync(0xffffffffu, p0, 1);
            p0 += __shfl_xor_sync(0xffffffffu, p0, 2);
            p1 += __shfl_xor_sync(0xffffffffu, p1, 1);
            p1 += __shfl_xor_sync(0xffffffffu, p1, 2);
            if (t == 0) {
                red[lr0 * 9 + warpN] = p0;
                red[(lr0 + 8) * 9 + warpN] = p1;
            }
        }
        __syncthreads();
        if (tid < BM) {
            int gr = rowBase + tid;
            if (gr < M) {
                al0[gr] = red[tid * 9 + 0] + red[tid * 9 + 1] +
                          red[tid * 9 + 2] + red[tid * 9 + 3];
                al1[gr] = red[tid * 9 + 4] + red[tid * 9 + 5] +
                          red[tid * 9 + 6] + red[tid * 9 + 7];
            }
        }
        __syncthreads();
    }
}

// ---------------------------------------------------------------------------
// Aggregation: one warp per target node; src table fp16 (uint2 = 4 halves
// per lane). 4+2+1 tails; streaming tgt/out.
// ---------------------------------------------------------------------------
__device__ __forceinline__ void acc_row(float4& acc, float a, uint2 u) {
    __half2 h0 = *(__half2*)&u.x;
    __half2 h1 = *(__half2*)&u.y;
    float2 f0 = __half22float2(h0);
    float2 f1 = __half22float2(h1);
    acc.x += a * f0.x; acc.y += a * f0.y;
    acc.z += a * f1.x; acc.w += a * f1.y;
}

__global__ __launch_bounds__(256)
void k_agg(const float4* __restrict__ tgt, const uint2* __restrict__ src,
           const float* __restrict__ att,
           const int* __restrict__ off, const int* __restrict__ csr,
           float4* __restrict__ out, int n) {
    int w = (blockIdx.x * blockDim.x + threadIdx.x) >> 5;
    int lid = threadIdx.x & 31;
    if (w >= n) return;
    int beg = off[w];
    int end = off[w + 1];
    float4 acc = make_float4(0.f, 0.f, 0.f, 0.f);
    float den = 0.f;
    int j = beg;
    for (; j + 3 < end; j += 4) {
        int s0 = csr[j + 0], s1 = csr[j + 1], s2 = csr[j + 2], s3 = csr[j + 3];
        float a0 = att[j + 0], a1 = att[j + 1], a2 = att[j + 2], a3 = att[j + 3];
        uint2 u0 = src[(size_t)s0 * 32 + lid];
        uint2 u1 = src[(size_t)s1 * 32 + lid];
        uint2 u2 = src[(size_t)s2 * 32 + lid];
        uint2 u3 = src[(size_t)s3 * 32 + lid];
        den += (a0 + a1) + (a2 + a3);
        acc_row(acc, a0, u0);
        acc_row(acc, a1, u1);
        acc_row(acc, a2, u2);
        acc_row(acc, a3, u3);
    }
    if (j + 1 < end) {
        int s0 = csr[j + 0], s1 = csr[j + 1];
        float a0 = att[j + 0], a1 = att[j + 1];
        uint2 u0 = src[(size_t)s0 * 32 + lid];
        uint2 u1 = src[(size_t)s1 * 32 + lid];
        den += a0 + a1;
        acc_row(acc, a0, u0);
        acc_row(acc, a1, u1);
        j += 2;
    }
    if (j < end) {
        int s0 = csr[j];
        float a0 = att[j];
        uint2 u0 = src[(size_t)s0 * 32 + lid];
        den += a0;
        acc_row(acc, a0, u0);
    }
    float inv = 1.0f / (den + EPSF);
    float4 tv = __ldcs(&tgt[(size_t)w * 32 + lid]);
    float4 r;
    r.x = fmaxf(tv.x + acc.x * inv, 0.f);
    r.y = fmaxf(tv.y + acc.y * inv, 0.f);
    r.z = fmaxf(tv.z + acc.z * inv, 0.f);
    r.w = fmaxf(tv.w + acc.w * inv, 0.f);
    __stcs(&out[(size_t)w * 32 + lid], r);
}

// ---------------------------------------------------------------------------
// Host launcher
// ---------------------------------------------------------------------------
static inline float* symf(const void* sym) {
    void* p = nullptr;
    cudaGetSymbolAddress(&p, sym);
    return (float*)p;
}
static inline int* symi(const void* sym) {
    void* p = nullptr;
    cudaGetSymbolAddress(&p, sym);
    return (int*)p;
}

extern "C" void kernel_launch(void* const* d_in, const int* in_sizes, int n_in,
                              void* d_out, int out_size) {
    const float* x_user = (const float*)d_in[0];
    const float* x_spot = (const float*)d_in[1];
    const int*   e_us   = (const int*)d_in[2];
    const int*   e_su   = (const int*)d_in[3];
    const float* Ws_us0 = (const float*)d_in[4];
    const float* Wt_us0 = (const float*)d_in[5];
    const float* a_us0  = (const float*)d_in[6];
    const float* Ws_su0 = (const float*)d_in[7];
    const float* Wt_su0 = (const float*)d_in[8];
    const float* a_su0  = (const float*)d_in[9];
    const float* Ws_us1 = (const float*)d_in[10];
    const float* Wt_us1 = (const float*)d_in[11];
    const float* a_us1  = (const float*)d_in[12];
    const float* Ws_su1 = (const float*)d_in[13];
    const float* Wt_su1 = (const float*)d_in[14];
    const float* a_su1  = (const float*)d_in[15];
    const float* W_ou   = (const float*)d_in[16];
    const float* b_ou   = (const float*)d_in[17];
    const float* W_os   = (const float*)d_in[18];
    const float* b_os   = (const float*)d_in[19];

    float* out = (float*)d_out;
    float* xu_out = out;
    float* xs_out = out + (size_t)N_USER * HID;
    float* ou_out = xs_out + (size_t)N_SPOT * HID;
    float* os_out = ou_out + (size_t)N_USER * OUTC;

    float* srcAh = symf(g_srcAh);
    float* srcBh = symf(g_srcBh);
    float* tgtA = symf(g_tgtA); float* tgtB = symf(g_tgtB);
    float* hu = symf(g_hu);     float* hs = symf(g_hs);
    float* alsA = symf(g_alsA); float* altA = symf(g_altA);
    float* alsB = symf(g_alsB); float* altB = symf(g_altB);
    int* si2_us = symi(g_si2_us); int* si2_su = symi(g_si2_su);
    int* cnt_us = symi(g_cnt_us); int* off_us = symi(g_off_us); int* cur_us = symi(g_cur_us);
    int* cnt_su = symi(g_cnt_su); int* off_su = symi(g_off_su); int* cur_su = symi(g_cur_su);
    int* csr_us = symi(g_csr_us); int* csr_su = symi(g_csr_su);
    int* row_us = symi(g_row_us); int* row_su = symi(g_row_su);
    float* attb = symf(g_att);

    const int EB = (EDG + 255) / 256;
    const int GP = 296;
    const int GP1 = 148;
    const int AU = (N_USER * 32 + 255) / 256;
    const int AS = (N_SPOT * 32 + 255) / 256;

    const int SM_L0 = (64 * (256 + 8) + 2 * 64 * (64 + 4) + 64 * 5) * 4;     // ~104 KB
    const int SM_L1 = (128 * (256 + 8) + 64 * (128 + 4) + 64 * 9) * 4;       // ~171 KB
    const int SM_FN = (128 * (64 + 8) + 2 * 64 * (128 + 4) + 64 * 5) * 4;    // ~106 KB

    cudaFuncSetAttribute((const void*)k_gemm_db<64, 256, true, false, true>,
                         cudaFuncAttributeMaxDynamicSharedMemorySize, SM_L0);
    cudaFuncSetAttribute((const void*)k_gemm_l1,
                         cudaFuncAttributeMaxDynamicSharedMemorySize, SM_L1);
    cudaFuncSetAttribute((const void*)k_gemm_db<128, 64, false, true, false>,
                         cudaFuncAttributeMaxDynamicSharedMemorySize, SM_FN);

    // ---- prep; launch #5 = L0 DB GEMM (profiled) ----
    k_gather2<<<EB, 256>>>(e_us, si2_us, EDG);                               // 0
    k_gather2<<<EB, 256>>>(e_su, si2_su, EDG);                               // 1
    cudaMemsetAsync(cnt_us, 0, sizeof(int) * (N_SPOT + 1));                  // 2
    cudaMemsetAsync(cnt_su, 0, sizeof(int) * (N_USER + 1));                  // 3
    k_hist<<<EB, 256>>>(e_us + EDG, cnt_us, EDG);                            // 4
    // x_user -> [srcA(fp16) | tgtB], alphas [alsA | altB]
    k_gemm_db<64, 256, true, false, true><<<GP, 256, SM_L0>>>(               // 5
        x_user, Ws_us0, Wt_su0, a_us0, a_su0 + HID, nullptr,
        srcAh, tgtB, alsA, altB, N_USER);
    k_hist<<<EB, 256>>>(e_su + EDG, cnt_su, EDG);
    k_scan<<<1, 1024>>>(cnt_us, off_us, cur_us, N_SPOT);
    k_scan<<<1, 1024>>>(cnt_su, off_su, cur_su, N_USER);
    k_scatter<<<EB, 256>>>(e_us + EDG, si2_us, cur_us, csr_us, row_us, EDG);
    k_scatter<<<EB, 256>>>(e_su + EDG, si2_su, cur_su, csr_su, row_su, EDG);
    // x_spot -> [srcB(fp16) | tgtA], alphas [alsB | altA]
    k_gemm_db<64, 256, true, false, true><<<GP, 256, SM_L0>>>(
        x_spot, Ws_su0, Wt_us0, a_su0, a_us0 + HID, nullptr,
        srcBh, tgtA, alsB, altA, N_SPOT);

    // ---- layer 0 aggregation ----
    k_att<<<EB, 256>>>(csr_us, row_us, alsA, altA, attb, EDG);
    k_agg<<<AS, 256>>>((const float4*)tgtA, (const uint2*)srcAh, attb,
                       off_us, csr_us, (float4*)hs, N_SPOT);
    k_att<<<EB, 256>>>(csr_su, row_su, alsB, altB, attb, EDG);
    k_agg<<<AU, 256>>>((const float4*)tgtB, (const uint2*)srcBh, attb,
                       off_su, csr_su, (float4*)hu, N_USER);

    // ---- layer 1 (K=128, fused, 512-thread high-occupancy variant) ----
    k_gemm_l1<<<GP1, 512, SM_L1>>>(
        hu, Ws_us1, Wt_su1, a_us1, a_su1 + HID,
        srcAh, tgtB, alsA, altB, N_USER);
    k_gemm_l1<<<GP1, 512, SM_L1>>>(
        hs, Ws_su1, Wt_us1, a_su1, a_us1 + HID,
        srcBh, tgtA, alsB, altA, N_SPOT);
    k_att<<<EB, 256>>>(csr_us, row_us, alsA, altA, attb, EDG);
    k_agg<<<AS, 256>>>((const float4*)tgtA, (const uint2*)srcAh, attb,
                       off_us, csr_us, (float4*)xs_out, N_SPOT);
    k_att<<<EB, 256>>>(csr_su, row_su, alsB, altB, attb, EDG);
    k_agg<<<AU, 256>>>((const float4*)tgtB, (const uint2*)srcBh, attb,
                       off_su, csr_su, (float4*)xu_out, N_USER);

    // ---- final per-type linear (K=128, N=64, bias; DB variant) ----
    k_gemm_db<128, 64, false, true, false><<<GP, 256, SM_FN>>>(
        xu_out, W_ou, nullptr, nullptr, nullptr, b_ou,
        ou_out, nullptr, nullptr, nullptr, N_USER);
    k_gemm_db<128, 64, false, true, false><<<GP, 256, SM_FN>>>(
        xs_out, W_os, nullptr, nullptr, nullptr, b_os,
        os_out, nullptr, nullptr, nullptr, N_SPOT);
}

// round 14
// speedup vs baseline: 1.7110x; 1.5945x over previous
#include <cuda_runtime.h>
#include <cuda_bf16.h>
#include <cuda_fp16.h>
#include <cstdint>

#define N_USER 100000
#define N_SPOT 100000
#define F_IN   64
#define HID    128
#define OUTC   64
#define EDG    500000
#define LEAK   0.2f
#define EPSF   1e-6f

// ---------------------------------------------------------------------------
// Scratch (device globals; no allocation allowed)
// ---------------------------------------------------------------------------
__device__ __half g_srcAh[(size_t)N_USER * HID];   // fp16 src tables (gathered)
__device__ __half g_srcBh[(size_t)N_SPOT * HID];
__device__ float g_tgtA[(size_t)N_SPOT * HID];
__device__ float g_tgtB[(size_t)N_USER * HID];
__device__ float g_hu[(size_t)N_USER * HID];
__device__ float g_hs[(size_t)N_SPOT * HID];

__device__ float g_alsA[N_USER];
__device__ float g_altA[N_SPOT];
__device__ float g_alsB[N_SPOT];
__device__ float g_altB[N_USER];

__device__ int g_si2_us[EDG];
__device__ int g_si2_su[EDG];
__device__ int g_cnt_us[N_SPOT + 1];
__device__ int g_off_us[N_SPOT + 1];
__device__ int g_cur_us[N_SPOT + 1];
__device__ int g_cnt_su[N_USER + 1];
__device__ int g_off_su[N_USER + 1];
__device__ int g_cur_su[N_USER + 1];
__device__ int g_csr_us[EDG];
__device__ int g_csr_su[EDG];
__device__ int g_row_us[EDG];
__device__ int g_row_su[EDG];
__device__ float g_att[EDG];
__device__ int g_bsum[1024];          // block sums for parallel scan

__device__ __forceinline__ float f2tf32(float x) {
    float y;
    asm("cvt.rna.tf32.f32 %0, %1;" : "=f"(y) : "f"(x));
    return y;
}
__device__ __forceinline__ uint32_t smem_u32(const void* p) {
    uint32_t a;
    asm("{ .reg .u64 t; cvta.to.shared.u64 t, %1; cvt.u32.u64 %0, t; }" : "=r"(a) : "l"(p));
    return a;
}
__device__ __forceinline__ void cp_async16(void* dst, const void* src) {
    asm volatile("cp.async.ca.shared.global [%0], [%1], 16;"
                 :: "r"(smem_u32(dst)), "l"(src) : "memory");
}
__device__ __forceinline__ void cp_commit() {
    asm volatile("cp.async.commit_group;" ::: "memory");
}
template <int NG>
__device__ __forceinline__ void cp_wait() {
    asm volatile("cp.async.wait_group %0;" :: "n"(NG) : "memory");
}

// ---------------------------------------------------------------------------
// Edge prep kernels
// ---------------------------------------------------------------------------
__global__ void k_gather2(const int* __restrict__ si, int* __restrict__ s2, int E) {
    int e = blockIdx.x * blockDim.x + threadIdx.x;
    if (e < E) {
        int a = si[e];
        s2[e] = si[a];
    }
}

__global__ void k_hist(const int* __restrict__ ti, int* __restrict__ cnt, int E) {
    int e = blockIdx.x * blockDim.x + threadIdx.x;
    if (e < E) atomicAdd(&cnt[ti[e]], 1);
}

// ---- 3-phase parallel prefix scan (coalesced) ----
// phase 1: per-block sums (1024 elems per block)
__global__ void k_scan1(const int* __restrict__ cnt, int* __restrict__ bsum, int n) {
    __shared__ int s[32];
    int tid = threadIdx.x;
    int i = blockIdx.x * 1024 + tid;
    int v = (i < n) ? cnt[i] : 0;
    int r = v;
#pragma unroll
    for (int d = 16; d; d >>= 1) r += __shfl_down_sync(0xffffffffu, r, d);
    if ((tid & 31) == 0) s[tid >> 5] = r;
    __syncthreads();
    if (tid < 32) {
        int t = s[tid];
#pragma unroll
        for (int d = 16; d; d >>= 1) t += __shfl_down_sync(0xffffffffu, t, d);
        if (tid == 0) bsum[blockIdx.x] = t;
    }
}

// phase 2: single-block exclusive scan of nb (<=1024) block sums
__global__ void k_scan2(int* __restrict__ bsum, int nb) {
    __shared__ int s[1024];
    int tid = threadIdx.x;
    int v = (tid < nb) ? bsum[tid] : 0;
    s[tid] = v;
    __syncthreads();
    for (int d = 1; d < 1024; d <<= 1) {
        int u = (tid >= d) ? s[tid - d] : 0;
        __syncthreads();
        s[tid] += u;
        __syncthreads();
    }
    if (tid < nb) bsum[tid] = s[tid] - v;   // exclusive base per block
}

// phase 3: block exclusive scan + base; writes off & cur; off[n] by last elem
__global__ void k_scan3(const int* __restrict__ cnt, const int* __restrict__ bsum,
                        int* __restrict__ off, int* __restrict__ cur, int n) {
    __shared__ int ws[32];
    int tid = threadIdx.x;
    int i = blockIdx.x * 1024 + tid;
    int v = (i < n) ? cnt[i] : 0;
    // warp inclusive scan
    int x = v;
#pragma unroll
    for (int d = 1; d < 32; d <<= 1) {
        int u = __shfl_up_sync(0xffffffffu, x, d);
        if ((tid & 31) >= d) x += u;
    }
    if ((tid & 31) == 31) ws[tid >> 5] = x;
    __syncthreads();
    if (tid < 32) {
        int t = ws[tid];
#pragma unroll
        for (int d = 1; d < 32; d <<= 1) {
            int u = __shfl_up_sync(0xffffffffu, t, d);
            if (tid >= d) t += u;
        }
        ws[tid] = t;
    }
    __syncthreads();
    int wbase = (tid >> 5) ? ws[(tid >> 5) - 1] : 0;
    int excl = bsum[blockIdx.x] + wbase + (x - v);
    if (i < n) {
        off[i] = excl;
        cur[i] = excl;
        if (i == n - 1) off[n] = excl + v;
    }
}

__global__ void k_scatter(const int* __restrict__ ti, const int* __restrict__ s2,
                          int* __restrict__ cur, int* __restrict__ csr,
                          int* __restrict__ rowOf, int E) {
    int e = blockIdx.x * blockDim.x + threadIdx.x;
    if (e < E) {
        int t = ti[e];
        int p = atomicAdd(&cur[t], 1);
        csr[p] = s2[e];
        rowOf[p] = t;
    }
}

__global__ void k_att(const int* __restrict__ csr, const int* __restrict__ rowOf,
                      const float* __restrict__ alpha_s, const float* __restrict__ alpha_t,
                      float* __restrict__ att, int E) {
    int j = blockIdx.x * blockDim.x + threadIdx.x;
    if (j < E) {
        float l = alpha_s[csr[j]] + alpha_t[rowOf[j]];
        l = (l > 0.f) ? l : LEAK * l;
        att[j] = __expf(l);
    }
}

// ---------------------------------------------------------------------------
// Shared epilogue store helper.
// When N==256 && H0: Y0 is an fp16 table (half2 stores), Y1 stays fp32.
// ---------------------------------------------------------------------------
template <int N, bool H0, bool BIAS>
__device__ __forceinline__ void store_pair(float* Y0, float* Y1,
                                           const float* bias,
                                           int r0, int M, int cb,
                                           float v0, float v1, float v2, float v3) {
    if (BIAS) {
        v0 += bias[cb]; v1 += bias[cb + 1];
        v2 += bias[cb]; v3 += bias[cb + 1];
    }
    if (N == 256) {
        bool hi = cb >= 128;
        int cc = cb & 127;
        if (!hi && H0) {
            __half* Yh = (__half*)Y0;
            __half2 h01 = __floats2half2_rn(v0, v1);
            __half2 h23 = __floats2half2_rn(v2, v3);
            if (r0 < M) *(__half2*)(Yh + (size_t)r0 * 128 + cc) = h01;
            if (r0 + 8 < M) *(__half2*)(Yh + (size_t)(r0 + 8) * 128 + cc) = h23;
        } else {
            float* Yt = hi ? Y1 : Y0;
            if (r0 < M) *(float2*)(Yt + (size_t)r0 * 128 + cc) = make_float2(v0, v1);
            if (r0 + 8 < M) *(float2*)(Yt + (size_t)(r0 + 8) * 128 + cc) = make_float2(v2, v3);
        }
    } else {
        if (BIAS) {
            if (r0 < M) __stcs((float2*)(Y0 + (size_t)r0 * N + cb), make_float2(v0, v1));
            if (r0 + 8 < M) __stcs((float2*)(Y0 + (size_t)(r0 + 8) * N + cb), make_float2(v2, v3));
        } else {
            if (r0 < M) *(float2*)(Y0 + (size_t)r0 * N + cb) = make_float2(v0, v1);
            if (r0 + 8 < M) *(float2*)(Y0 + (size_t)(r0 + 8) * N + cb) = make_float2(v2, v3);
        }
    }
}

// ---------------------------------------------------------------------------
// k_gemm_db: persistent, cp.async double-buffered A (in-smem tf32 convert),
//            W resident, 2 CTAs/SM. L0 (64,256,H0) and FN (128,64).
// ---------------------------------------------------------------------------
template <int K, int N, bool ALPHA, bool BIAS, bool H0>
__global__ __launch_bounds__(256, 2)
void k_gemm_db(const float* __restrict__ X,
               const float* __restrict__ W0, const float* __restrict__ W1,
               const float* __restrict__ av0, const float* __restrict__ av1,
               const float* __restrict__ bias,
               float* __restrict__ Y0, float* __restrict__ Y1,
               float* __restrict__ al0, float* __restrict__ al1, int M) {
    constexpr int BM = 64;
    constexpr int KP = K + 4;
    constexpr int NP = N + 8;
    constexpr int WN = N / 4;
    constexpr int NT = WN / 8;
    constexpr int XF = BM * K / 1024;
    extern __shared__ float smf[];
    float* Wsm = smf;                     // [K][NP]
    float* A0  = smf + K * NP;            // [BM][KP] x2
    float* A1  = A0 + BM * KP;
    float* red = A1 + BM * KP;            // [BM][5]

    const int tid = threadIdx.x;
    const int wid = tid >> 5;
    const int lane = tid & 31;
    const int warpM = wid >> 2;
    const int warpN = wid & 3;
    const int q = lane >> 2;
    const int t = lane & 3;

    for (int i = tid; i < K * N / 4; i += 256) {
        int k = i / (N / 4);
        int n4 = (i % (N / 4)) * 4;
        const float* src = (N == 256)
            ? ((n4 < 128) ? (W0 + (size_t)k * 128 + n4) : (W1 + (size_t)k * 128 + (n4 - 128)))
            : (W0 + (size_t)k * N + n4);
        float4 v = *(const float4*)src;
        v.x = f2tf32(v.x); v.y = f2tf32(v.y); v.z = f2tf32(v.z); v.w = f2tf32(v.w);
        *(float4*)(Wsm + k * NP + n4) = v;
    }

    const int ntiles = (M + BM - 1) / BM;

    if ((int)blockIdx.x < ntiles) {
#pragma unroll
        for (int f = 0; f < XF; f++) {
            int i = tid + f * 256;
            int r = i / (K / 4);
            int c4 = (i % (K / 4)) * 4;
            int gr = blockIdx.x * BM + r;
            if (gr >= M) gr = M - 1;
            cp_async16(A0 + r * KP + c4, X + (size_t)gr * K + c4);
        }
    }
    cp_commit();

    int it = 0;
    for (int tile = blockIdx.x; tile < ntiles; tile += gridDim.x, it++) {
        float* curA = (it & 1) ? A1 : A0;
        float* nxtA = (it & 1) ? A0 : A1;

        int next = tile + gridDim.x;
        if (next < ntiles) {
#pragma unroll
            for (int f = 0; f < XF; f++) {
                int i = tid + f * 256;
                int r = i / (K / 4);
                int c4 = (i % (K / 4)) * 4;
                int gr = next * BM + r;
                if (gr >= M) gr = M - 1;
                cp_async16(nxtA + r * KP + c4, X + (size_t)gr * K + c4);
            }
        }
        cp_commit();
        cp_wait<1>();
#pragma unroll
        for (int f = 0; f < XF; f++) {
            int i = tid + f * 256;
            int r = i / (K / 4);
            int c4 = (i % (K / 4)) * 4;
            float4 v = *(const float4*)(curA + r * KP + c4);
            v.x = f2tf32(v.x); v.y = f2tf32(v.y); v.z = f2tf32(v.z); v.w = f2tf32(v.w);
            *(float4*)(curA + r * KP + c4) = v;
        }
        __syncthreads();

        float acc[2][NT][4];
#pragma unroll
        for (int mt = 0; mt < 2; mt++)
#pragma unroll
            for (int nt = 0; nt < NT; nt++)
#pragma unroll
                for (int j = 0; j < 4; j++) acc[mt][nt][j] = 0.f;

        const uint32_t* Au = (const uint32_t*)curA;
        const uint32_t* Bu = (const uint32_t*)Wsm;

#pragma unroll
        for (int kk = 0; kk < K; kk += 8) {
            uint32_t a[2][4];
#pragma unroll
            for (int mt = 0; mt < 2; mt++) {
                int r0 = warpM * 32 + mt * 16 + q;
                a[mt][0] = Au[r0 * KP + kk + t];
                a[mt][1] = Au[(r0 + 8) * KP + kk + t];
                a[mt][2] = Au[r0 * KP + kk + 4 + t];
                a[mt][3] = Au[(r0 + 8) * KP + kk + 4 + t];
            }
            uint32_t b[NT][2];
#pragma unroll
            for (int nt = 0; nt < NT; nt++) {
                int nc = warpN * WN + nt * 8 + q;
                b[nt][0] = Bu[(kk + t) * NP + nc];
                b[nt][1] = Bu[(kk + 4 + t) * NP + nc];
            }
#pragma unroll
            for (int mt = 0; mt < 2; mt++)
#pragma unroll
                for (int nt = 0; nt < NT; nt++) {
                    asm("mma.sync.aligned.m16n8k8.row.col.f32.tf32.tf32.f32 "
                        "{%0,%1,%2,%3}, {%4,%5,%6,%7}, {%8,%9}, {%0,%1,%2,%3};"
                        : "+f"(acc[mt][nt][0]), "+f"(acc[mt][nt][1]),
                          "+f"(acc[mt][nt][2]), "+f"(acc[mt][nt][3])
                        : "r"(a[mt][0]), "r"(a[mt][1]), "r"(a[mt][2]), "r"(a[mt][3]),
                          "r"(b[nt][0]), "r"(b[nt][1]));
                }
        }

        const int rowBase = tile * BM;
#pragma unroll
        for (int mt = 0; mt < 2; mt++) {
            int lr0 = warpM * 32 + mt * 16 + q;
            int r0 = rowBase + lr0;
            float p0 = 0.f, p1 = 0.f;
#pragma unroll
            for (int nt = 0; nt < NT; nt++) {
                int cb = warpN * WN + nt * 8 + t * 2;
                float v0 = acc[mt][nt][0], v1 = acc[mt][nt][1];
                float v2 = acc[mt][nt][2], v3 = acc[mt][nt][3];
                store_pair<N, H0, BIAS>(Y0, Y1, bias, r0, M, cb, v0, v1, v2, v3);
                if (ALPHA) {
                    const float* avt = (N == 256 && cb >= 128) ? av1 : av0;
                    int cc = (N == 256) ? (cb & 127) : cb;
                    float a0 = avt[cc], a1 = avt[cc + 1];
                    p0 += v0 * a0 + v1 * a1;
                    p1 += v2 * a0 + v3 * a1;
                }
            }
            if (ALPHA) {
                p0 += __shfl_xor_sync(0xffffffffu, p0, 1);
                p0 += __shfl_xor_sync(0xffffffffu, p0, 2);
                p1 += __shfl_xor_sync(0xffffffffu, p1, 1);
                p1 += __shfl_xor_sync(0xffffffffu, p1, 2);
                if (t == 0) {
                    red[lr0 * 5 + warpN] = p0;
                    red[(lr0 + 8) * 5 + warpN] = p1;
                }
            }
        }
        __syncthreads();
        if (ALPHA) {
            if (tid < BM) {
                int gr = rowBase + tid;
                if (gr < M) {
                    al0[gr] = red[tid * 5 + 0] + red[tid * 5 + 1];
                    al1[gr] = red[tid * 5 + 2] + red[tid * 5 + 3];
                }
            }
            __syncthreads();
        }
    }
}

// ---------------------------------------------------------------------------
// k_gemm_l1: fused L1 GEMM (K=128, N=256), 512 threads = 16 warps
// (2M x 8N, warp tile 32x32). W resident, register-prefetch A. 1 CTA/SM.
// Y0 = fp16 table; dual fused alpha.
// ---------------------------------------------------------------------------
__global__ __launch_bounds__(512, 1)
void k_gemm_l1(const float* __restrict__ X,
               const float* __restrict__ W0, const float* __restrict__ W1,
               const float* __restrict__ av0, const float* __restrict__ av1,
               float* __restrict__ Y0, float* __restrict__ Y1,
               float* __restrict__ al0, float* __restrict__ al1, int M) {
    constexpr int K = 128;
    constexpr int N = 256;
    constexpr int BM = 64;
    constexpr int KP = K + 4;
    constexpr int NP = N + 8;
    constexpr int WN = 32;
    constexpr int NT = 4;
    constexpr int XF = BM * K / (512 * 4);
    extern __shared__ float smf[];
    float* Wsm = smf;                 // [K][NP]
    float* As  = smf + K * NP;        // [BM][KP]
    float* red = As + BM * KP;        // [BM][9]

    const int tid = threadIdx.x;
    const int wid = tid >> 5;
    const int lane = tid & 31;
    const int warpM = wid >> 3;
    const int warpN = wid & 7;
    const int q = lane >> 2;
    const int t = lane & 3;

    for (int i = tid; i < K * N / 4; i += 512) {
        int k = i / (N / 4);
        int n4 = (i % (N / 4)) * 4;
        const float* src = (n4 < 128) ? (W0 + (size_t)k * 128 + n4)
                                      : (W1 + (size_t)k * 128 + (n4 - 128));
        float4 v = *(const float4*)src;
        v.x = f2tf32(v.x); v.y = f2tf32(v.y); v.z = f2tf32(v.z); v.w = f2tf32(v.w);
        *(float4*)(Wsm + k * NP + n4) = v;
    }

    const int ntiles = (M + BM - 1) / BM;
    int tile = blockIdx.x;
    float4 xr[XF];

    if (tile < ntiles) {
#pragma unroll
        for (int f = 0; f < XF; f++) {
            int i = tid + f * 512;
            int r = i >> 5;
            int c4 = (i & 31) * 4;
            int gr = tile * BM + r;
            xr[f] = (gr < M) ? *(const float4*)(X + (size_t)gr * K + c4)
                             : make_float4(0.f, 0.f, 0.f, 0.f);
        }
    }
    __syncthreads();

    for (; tile < ntiles; tile += gridDim.x) {
#pragma unroll
        for (int f = 0; f < XF; f++) {
            int i = tid + f * 512;
            int r = i >> 5;
            int c4 = (i & 31) * 4;
            float4 v = xr[f];
            v.x = f2tf32(v.x); v.y = f2tf32(v.y); v.z = f2tf32(v.z); v.w = f2tf32(v.w);
            *(float4*)(As + r * KP + c4) = v;
        }
        __syncthreads();

        int next = tile + gridDim.x;
        if (next < ntiles) {
#pragma unroll
            for (int f = 0; f < XF; f++) {
                int i = tid + f * 512;
                int r = i >> 5;
                int c4 = (i & 31) * 4;
                int gr = next * BM + r;
                xr[f] = (gr < M) ? *(const float4*)(X + (size_t)gr * K + c4)
                                 : make_float4(0.f, 0.f, 0.f, 0.f);
            }
        }

        float acc[2][NT][4];
#pragma unroll
        for (int mt = 0; mt < 2; mt++)
#pragma unroll
            for (int nt = 0; nt < NT; nt++)
#pragma unroll
                for (int j = 0; j < 4; j++) acc[mt][nt][j] = 0.f;

        const uint32_t* Au = (const uint32_t*)As;
        const uint32_t* Bu = (const uint32_t*)Wsm;

#pragma unroll
        for (int kk = 0; kk < K; kk += 8) {
            uint32_t a[2][4];
#pragma unroll
            for (int mt = 0; mt < 2; mt++) {
                int r0 = warpM * 32 + mt * 16 + q;
                a[mt][0] = Au[r0 * KP + kk + t];
                a[mt][1] = Au[(r0 + 8) * KP + kk + t];
                a[mt][2] = Au[r0 * KP + kk + 4 + t];
                a[mt][3] = Au[(r0 + 8) * KP + kk + 4 + t];
            }
            uint32_t b[NT][2];
#pragma unroll
            for (int nt = 0; nt < NT; nt++) {
                int nc = warpN * WN + nt * 8 + q;
                b[nt][0] = Bu[(kk + t) * NP + nc];
                b[nt][1] = Bu[(kk + 4 + t) * NP + nc];
            }
#pragma unroll
            for (int mt = 0; mt < 2; mt++)
#pragma unroll
                for (int nt = 0; nt < NT; nt++) {
                    asm("mma.sync.aligned.m16n8k8.row.col.f32.tf32.tf32.f32 "
                        "{%0,%1,%2,%3}, {%4,%5,%6,%7}, {%8,%9}, {%0,%1,%2,%3};"
                        : "+f"(acc[mt][nt][0]), "+f"(acc[mt][nt][1]),
                          "+f"(acc[mt][nt][2]), "+f"(acc[mt][nt][3])
                        : "r"(a[mt][0]), "r"(a[mt][1]), "r"(a[mt][2]), "r"(a[mt][3]),
                          "r"(b[nt][0]), "r"(b[nt][1]));
                }
        }

        const int rowBase = tile * BM;
#pragma unroll
        for (int mt = 0; mt < 2; mt++) {
            int lr0 = warpM * 32 + mt * 16 + q;
            int r0 = rowBase + lr0;
            float p0 = 0.f, p1 = 0.f;
#pragma unroll
            for (int nt = 0; nt < NT; nt++) {
                int cb = warpN * WN + nt * 8 + t * 2;
                float v0 = acc[mt][nt][0], v1 = acc[mt][nt][1];
                float v2 = acc[mt][nt][2], v3 = acc[mt][nt][3];
                store_pair<256, true, false>(Y0, Y1, nullptr, r0, M, cb, v0, v1, v2, v3);
                const float* avt = (cb >= 128) ? av1 : av0;
                int cc = cb & 127;
                float a0 = avt[cc], a1 = avt[cc + 1];
                p0 += v0 * a0 + v1 * a1;
                p1 += v2 * a0 + v3 * a1;
            }
            p0 += __shfl_xor_sync(0xffffffffu, p0, 1);
            p0 += __shfl_xor_sync(0xffffffffu, p0, 2);
            p1 += __shfl_xor_sync(0xffffffffu, p1, 1);
            p1 += __shfl_xor_sync(0xffffffffu, p1, 2);
            if (t == 0) {
                red[lr0 * 9 + warpN] = p0;
                red[(lr0 + 8) * 9 + warpN] = p1;
            }
        }
        __syncthreads();
        if (tid < BM) {
            int gr = rowBase + tid;
            if (gr < M) {
                al0[gr] = red[tid * 9 + 0] + red[tid * 9 + 1] +
                          red[tid * 9 + 2] + red[tid * 9 + 3];
                al1[gr] = red[tid * 9 + 4] + red[tid * 9 + 5] +
                          red[tid * 9 + 6] + red[tid * 9 + 7];
            }
        }
        __syncthreads();
    }
}

// ---------------------------------------------------------------------------
// Aggregation: one warp per target node; src table fp16 (uint2 = 4 halves
// per lane). 4+2+1 tails; streaming tgt/out.
// ---------------------------------------------------------------------------
__device__ __forceinline__ void acc_row(float4& acc, float a, uint2 u) {
    __half2 h0 = *(__half2*)&u.x;
    __half2 h1 = *(__half2*)&u.y;
    float2 f0 = __half22float2(h0);
    float2 f1 = __half22float2(h1);
    acc.x += a * f0.x; acc.y += a * f0.y;
    acc.z += a * f1.x; acc.w += a * f1.y;
}

__global__ __launch_bounds__(256)
void k_agg(const float4* __restrict__ tgt, const uint2* __restrict__ src,
           const float* __restrict__ att,
           const int* __restrict__ off, const int* __restrict__ csr,
           float4* __restrict__ out, int n) {
    int w = (blockIdx.x * blockDim.x + threadIdx.x) >> 5;
    int lid = threadIdx.x & 31;
    if (w >= n) return;
    int beg = off[w];
    int end = off[w + 1];
    float4 acc = make_float4(0.f, 0.f, 0.f, 0.f);
    float den = 0.f;
    int j = beg;
    for (; j + 3 < end; j += 4) {
        int s0 = csr[j + 0], s1 = csr[j + 1], s2 = csr[j + 2], s3 = csr[j + 3];
        float a0 = att[j + 0], a1 = att[j + 1], a2 = att[j + 2], a3 = att[j + 3];
        uint2 u0 = src[(size_t)s0 * 32 + lid];
        uint2 u1 = src[(size_t)s1 * 32 + lid];
        uint2 u2 = src[(size_t)s2 * 32 + lid];
        uint2 u3 = src[(size_t)s3 * 32 + lid];
        den += (a0 + a1) + (a2 + a3);
        acc_row(acc, a0, u0);
        acc_row(acc, a1, u1);
        acc_row(acc, a2, u2);
        acc_row(acc, a3, u3);
    }
    if (j + 1 < end) {
        int s0 = csr[j + 0], s1 = csr[j + 1];
        float a0 = att[j + 0], a1 = att[j + 1];
        uint2 u0 = src[(size_t)s0 * 32 + lid];
        uint2 u1 = src[(size_t)s1 * 32 + lid];
        den += a0 + a1;
        acc_row(acc, a0, u0);
        acc_row(acc, a1, u1);
        j += 2;
    }
    if (j < end) {
        int s0 = csr[j];
        float a0 = att[j];
        uint2 u0 = src[(size_t)s0 * 32 + lid];
        den += a0;
        acc_row(acc, a0, u0);
    }
    float inv = 1.0f / (den + EPSF);
    float4 tv = __ldcs(&tgt[(size_t)w * 32 + lid]);
    float4 r;
    r.x = fmaxf(tv.x + acc.x * inv, 0.f);
    r.y = fmaxf(tv.y + acc.y * inv, 0.f);
    r.z = fmaxf(tv.z + acc.z * inv, 0.f);
    r.w = fmaxf(tv.w + acc.w * inv, 0.f);
    __stcs(&out[(size_t)w * 32 + lid], r);
}

// ---------------------------------------------------------------------------
// Host launcher
// ---------------------------------------------------------------------------
static inline float* symf(const void* sym) {
    void* p = nullptr;
    cudaGetSymbolAddress(&p, sym);
    return (float*)p;
}
static inline int* symi(const void* sym) {
    void* p = nullptr;
    cudaGetSymbolAddress(&p, sym);
    return (int*)p;
}

extern "C" void kernel_launch(void* const* d_in, const int* in_sizes, int n_in,
                              void* d_out, int out_size) {
    const float* x_user = (const float*)d_in[0];
    const float* x_spot = (const float*)d_in[1];
    const int*   e_us   = (const int*)d_in[2];
    const int*   e_su   = (const int*)d_in[3];
    const float* Ws_us0 = (const float*)d_in[4];
    const float* Wt_us0 = (const float*)d_in[5];
    const float* a_us0  = (const float*)d_in[6];
    const float* Ws_su0 = (const float*)d_in[7];
    const float* Wt_su0 = (const float*)d_in[8];
    const float* a_su0  = (const float*)d_in[9];
    const float* Ws_us1 = (const float*)d_in[10];
    const float* Wt_us1 = (const float*)d_in[11];
    const float* a_us1  = (const float*)d_in[12];
    const float* Ws_su1 = (const float*)d_in[13];
    const float* Wt_su1 = (const float*)d_in[14];
    const float* a_su1  = (const float*)d_in[15];
    const float* W_ou   = (const float*)d_in[16];
    const float* b_ou   = (const float*)d_in[17];
    const float* W_os   = (const float*)d_in[18];
    const float* b_os   = (const float*)d_in[19];

    float* out = (float*)d_out;
    float* xu_out = out;
    float* xs_out = out + (size_t)N_USER * HID;
    float* ou_out = xs_out + (size_t)N_SPOT * HID;
    float* os_out = ou_out + (size_t)N_USER * OUTC;

    float* srcAh = symf(g_srcAh);
    float* srcBh = symf(g_srcBh);
    float* tgtA = symf(g_tgtA); float* tgtB = symf(g_tgtB);
    float* hu = symf(g_hu);     float* hs = symf(g_hs);
    float* alsA = symf(g_alsA); float* altA = symf(g_altA);
    float* alsB = symf(g_alsB); float* altB = symf(g_altB);
    int* si2_us = symi(g_si2_us); int* si2_su = symi(g_si2_su);
    int* cnt_us = symi(g_cnt_us); int* off_us = symi(g_off_us); int* cur_us = symi(g_cur_us);
    int* cnt_su = symi(g_cnt_su); int* off_su = symi(g_off_su); int* cur_su = symi(g_cur_su);
    int* csr_us = symi(g_csr_us); int* csr_su = symi(g_csr_su);
    int* row_us = symi(g_row_us); int* row_su = symi(g_row_su);
    float* attb = symf(g_att);
    int* bsum = symi(g_bsum);

    const int EB = (EDG + 255) / 256;
    const int GP = 296;
    const int GP1 = 148;
    const int AU = (N_USER * 32 + 255) / 256;
    const int AS = (N_SPOT * 32 + 255) / 256;
    const int SB = (N_USER + 1023) / 1024;   // 98 scan blocks (same for spot)

    const int SM_L0 = (64 * (256 + 8) + 2 * 64 * (64 + 4) + 64 * 5) * 4;     // ~104 KB
    const int SM_L1 = (128 * (256 + 8) + 64 * (128 + 4) + 64 * 9) * 4;       // ~171 KB
    const int SM_FN = (128 * (64 + 8) + 2 * 64 * (128 + 4) + 64 * 5) * 4;    // ~106 KB

    cudaFuncSetAttribute((const void*)k_gemm_db<64, 256, true, false, true>,
                         cudaFuncAttributeMaxDynamicSharedMemorySize, SM_L0);
    cudaFuncSetAttribute((const void*)k_gemm_l1,
                         cudaFuncAttributeMaxDynamicSharedMemorySize, SM_L1);
    cudaFuncSetAttribute((const void*)k_gemm_db<128, 64, false, true, false>,
                         cudaFuncAttributeMaxDynamicSharedMemorySize, SM_FN);

    // ---- prep; launch #5 = L0 DB GEMM (profiled) ----
    k_gather2<<<EB, 256>>>(e_us, si2_us, EDG);                               // 0
    k_gather2<<<EB, 256>>>(e_su, si2_su, EDG);                               // 1
    cudaMemsetAsync(cnt_us, 0, sizeof(int) * (N_SPOT + 1));                  // 2
    cudaMemsetAsync(cnt_su, 0, sizeof(int) * (N_USER + 1));                  // 3
    k_hist<<<EB, 256>>>(e_us + EDG, cnt_us, EDG);                            // 4
    // x_user -> [srcA(fp16) | tgtB], alphas [alsA | altB]
    k_gemm_db<64, 256, true, false, true><<<GP, 256, SM_L0>>>(               // 5
        x_user, Ws_us0, Wt_su0, a_us0, a_su0 + HID, nullptr,
        srcAh, tgtB, alsA, altB, N_USER);
    k_hist<<<EB, 256>>>(e_su + EDG, cnt_su, EDG);
    // parallel scans (coalesced, full-chip)
    k_scan1<<<SB, 1024>>>(cnt_us, bsum, N_SPOT);
    k_scan2<<<1, 1024>>>(bsum, SB);
    k_scan3<<<SB, 1024>>>(cnt_us, bsum, off_us, cur_us, N_SPOT);
    k_scan1<<<SB, 1024>>>(cnt_su, bsum, N_USER);
    k_scan2<<<1, 1024>>>(bsum, SB);
    k_scan3<<<SB, 1024>>>(cnt_su, bsum, off_su, cur_su, N_USER);
    k_scatter<<<EB, 256>>>(e_us + EDG, si2_us, cur_us, csr_us, row_us, EDG);
    k_scatter<<<EB, 256>>>(e_su + EDG, si2_su, cur_su, csr_su, row_su, EDG);
    // x_spot -> [srcB(fp16) | tgtA], alphas [alsB | altA]
    k_gemm_db<64, 256, true, false, true><<<GP, 256, SM_L0>>>(
        x_spot, Ws_su0, Wt_us0, a_su0, a_us0 + HID, nullptr,
        srcBh, tgtA, alsB, altA, N_SPOT);

    // ---- layer 0 aggregation ----
    k_att<<<EB, 256>>>(csr_us, row_us, alsA, altA, attb, EDG);
    k_agg<<<AS, 256>>>((const float4*)tgtA, (const uint2*)srcAh, attb,
                       off_us, csr_us, (float4*)hs, N_SPOT);
    k_att<<<EB, 256>>>(csr_su, row_su, alsB, altB, attb, EDG);
    k_agg<<<AU, 256>>>((const float4*)tgtB, (const uint2*)srcBh, attb,
                       off_su, csr_su, (float4*)hu, N_USER);

    // ---- layer 1 (K=128, fused, 512-thread variant) ----
    k_gemm_l1<<<GP1, 512, SM_L1>>>(
        hu, Ws_us1, Wt_su1, a_us1, a_su1 + HID,
        srcAh, tgtB, alsA, altB, N_USER);
    k_gemm_l1<<<GP1, 512, SM_L1>>>(
        hs, Ws_su1, Wt_us1, a_su1, a_us1 + HID,
        srcBh, tgtA, alsB, altA, N_SPOT);
    k_att<<<EB, 256>>>(csr_us, row_us, alsA, altA, attb, EDG);
    k_agg<<<AS, 256>>>((const float4*)tgtA, (const uint2*)srcAh, attb,
                       off_us, csr_us, (float4*)xs_out, N_SPOT);
    k_att<<<EB, 256>>>(csr_su, row_su, alsB, altB, attb, EDG);
    k_agg<<<AU, 256>>>((const float4*)tgtB, (const uint2*)srcBh, attb,
                       off_su, csr_su, (float4*)xu_out, N_USER);

    // ---- final per-type linear (K=128, N=64, bias; DB variant) ----
    k_gemm_db<128, 64, false, true, false><<<GP, 256, SM_FN>>>(
        xu_out, W_ou, nullptr, nullptr, nullptr, b_ou,
        ou_out, nullptr, nullptr, nullptr, N_USER);
    k_gemm_db<128, 64, false, true, false><<<GP, 256, SM_FN>>>(
        xs_out, W_os, nullptr, nullptr, nullptr, b_os,
        os_out, nullptr, nullptr, nullptr, N_SPOT);
}